// round 1
// baseline (speedup 1.0000x reference)
#include <cuda_runtime.h>
#include <cstdint>

#define B_ 2
#define T_ 2048
#define E_ 2048
#define H_ 32
#define D_ 64
#define THREE_E (3 * E_)

// Scratch: qkv projection output and attention output (no allocs allowed).
__device__ float g_qkv[(size_t)B_ * T_ * THREE_E];   // 96 MB
__device__ float g_att[(size_t)B_ * T_ * E_];        // 32 MB

// ---------------------------------------------------------------------------
// SGEMM: C[M,N] = A[M,K] @ B[K,N] + bias[N]   (all row-major, fp32)
// 128x128 block tile, BK=8, 256 threads, 8x8 per-thread microtile.
// ---------------------------------------------------------------------------
#define BM 128
#define BN 128
#define BK 8
#define TM 8
#define TN 8

__global__ __launch_bounds__(256, 2)
void sgemm_bias(int M, int N, int K,
                const float* __restrict__ A,
                const float* __restrict__ Bm,
                const float* __restrict__ bias,
                float* __restrict__ C) {
    __shared__ float As[BK][BM];
    __shared__ float Bs[BK][BN];

    const int tid = threadIdx.x;
    const int brow = blockIdx.y;
    const int bcol = blockIdx.x;

    const int tcol = tid % (BN / TN);   // 0..15
    const int trow = tid / (BN / TN);   // 0..15

    // global load indices
    const int aRow = tid >> 1;          // 0..127
    const int aCol = (tid & 1) * 4;     // 0 or 4
    const int bRow = tid >> 5;          // 0..7
    const int bCol = (tid & 31) * 4;    // 0..124

    const float* Ab = A + (size_t)(brow * BM) * K;
    const float* Bb = Bm + bcol * BN;

    float acc[TM][TN];
#pragma unroll
    for (int i = 0; i < TM; i++)
#pragma unroll
        for (int j = 0; j < TN; j++) acc[i][j] = 0.0f;

    float regA[TM], regB[TN];

    for (int k0 = 0; k0 < K; k0 += BK) {
        float4 a4 = *(const float4*)(Ab + (size_t)aRow * K + k0 + aCol);
        As[aCol + 0][aRow] = a4.x;
        As[aCol + 1][aRow] = a4.y;
        As[aCol + 2][aRow] = a4.z;
        As[aCol + 3][aRow] = a4.w;
        float4 b4 = *(const float4*)(Bb + (size_t)(k0 + bRow) * N + bCol);
        *(float4*)&Bs[bRow][bCol] = b4;
        __syncthreads();

#pragma unroll
        for (int kk = 0; kk < BK; kk++) {
#pragma unroll
            for (int i = 0; i < TM; i++) regA[i] = As[kk][trow * TM + i];
#pragma unroll
            for (int j = 0; j < TN; j++) regB[j] = Bs[kk][tcol * TN + j];
#pragma unroll
            for (int i = 0; i < TM; i++)
#pragma unroll
                for (int j = 0; j < TN; j++)
                    acc[i][j] = fmaf(regA[i], regB[j], acc[i][j]);
        }
        __syncthreads();
    }

    const int crow0 = brow * BM + trow * TM;
    const int ccol0 = bcol * BN + tcol * TN;
#pragma unroll
    for (int i = 0; i < TM; i++) {
        float* crow = C + (size_t)(crow0 + i) * N + ccol0;
#pragma unroll
        for (int j = 0; j < TN; j += 4) {
            float4 v;
            v.x = acc[i][j + 0] + bias[ccol0 + j + 0];
            v.y = acc[i][j + 1] + bias[ccol0 + j + 1];
            v.z = acc[i][j + 2] + bias[ccol0 + j + 2];
            v.w = acc[i][j + 3] + bias[ccol0 + j + 3];
            *(float4*)(crow + j) = v;
        }
    }
}

// ---------------------------------------------------------------------------
// Flash attention fp32 with ALiBi + causal mask.
// Grid: (T/64, B*H). Block: 256 threads.
// Each thread: 4 q-rows (4*tq..4*tq+3) x 4 k-cols / d-cols (tk+16*j).
// Dynamic smem: Qs, Ks, Vs, Ps each [64][65] floats.
// ---------------------------------------------------------------------------
#define FPAD 65
#define FLASH_SMEM (4 * 64 * FPAD * (int)sizeof(float))

__global__ __launch_bounds__(256, 3)
void flash_kernel(const float* __restrict__ qkv, float* __restrict__ out) {
    extern __shared__ float smem[];
    float (*Qs)[FPAD] = (float(*)[FPAD])(smem);
    float (*Ks)[FPAD] = (float(*)[FPAD])(smem + 64 * FPAD);
    float (*Vs)[FPAD] = (float(*)[FPAD])(smem + 2 * 64 * FPAD);
    float (*Ps)[FPAD] = (float(*)[FPAD])(smem + 3 * 64 * FPAD);

    const int tid = threadIdx.x;
    const int tk = tid & 15;    // k/d column group
    const int tq = tid >> 4;    // q row group (0..15)

    const int qb = blockIdx.x;
    const int bh = blockIdx.y;
    const int b = bh >> 5;
    const int h = bh & 31;

    const float slope = exp2f(-0.25f * (float)(h + 1));
    const float scale = 8.0f / (float)D_;

    const size_t base = (size_t)b * T_ * THREE_E;
    const float* Qg = qkv + base + (size_t)h * D_;
    const float* Kg = qkv + base + E_ + (size_t)h * D_;
    const float* Vg = qkv + base + 2 * E_ + (size_t)h * D_;

    const int q0 = qb * 64;

    // load Q tile, pre-scaled
    for (int i = tid; i < 64 * 64; i += 256) {
        int r = i >> 6, c = i & 63;
        Qs[r][c] = Qg[(size_t)(q0 + r) * THREE_E + c] * scale;
    }

    float m[4], l[4], acc[4][4];
#pragma unroll
    for (int i = 0; i < 4; i++) {
        m[i] = -1e30f;
        l[i] = 0.0f;
#pragma unroll
        for (int j = 0; j < 4; j++) acc[i][j] = 0.0f;
    }

    const int nkb = qb + 1;   // causal: only K-blocks up to the diagonal
    for (int kb = 0; kb < nkb; kb++) {
        __syncthreads();   // previous iter's PV reads of Ks/Vs/Ps done
        for (int i = tid; i < 64 * 64; i += 256) {
            int r = i >> 6, c = i & 63;
            size_t goff = (size_t)(kb * 64 + r) * THREE_E + c;
            Ks[r][c] = Kg[goff];
            Vs[r][c] = Vg[goff];
        }
        __syncthreads();

        // S = Qs @ Ks^T
        float s[4][4];
#pragma unroll
        for (int i = 0; i < 4; i++)
#pragma unroll
            for (int j = 0; j < 4; j++) s[i][j] = 0.0f;

        for (int d = 0; d < 64; d++) {
            float qv[4], kv[4];
#pragma unroll
            for (int i = 0; i < 4; i++) qv[i] = Qs[4 * tq + i][d];
#pragma unroll
            for (int j = 0; j < 4; j++) kv[j] = Ks[tk + 16 * j][d];
#pragma unroll
            for (int i = 0; i < 4; i++)
#pragma unroll
                for (int j = 0; j < 4; j++)
                    s[i][j] = fmaf(qv[i], kv[j], s[i][j]);
        }

        // ALiBi bias + causal mask
#pragma unroll
        for (int i = 0; i < 4; i++) {
            const int qg = q0 + 4 * tq + i;
#pragma unroll
            for (int j = 0; j < 4; j++) {
                const int kg = kb * 64 + tk + 16 * j;
                s[i][j] = (kg > qg) ? -1e30f
                                    : s[i][j] + slope * (float)(kg - qg);
            }
        }

        // row max over this k-block
        float mloc[4];
#pragma unroll
        for (int i = 0; i < 4; i++) {
            mloc[i] = fmaxf(fmaxf(s[i][0], s[i][1]), fmaxf(s[i][2], s[i][3]));
        }
#pragma unroll
        for (int o = 1; o < 16; o <<= 1) {
#pragma unroll
            for (int i = 0; i < 4; i++)
                mloc[i] = fmaxf(mloc[i], __shfl_xor_sync(0xffffffffu, mloc[i], o));
        }

        float alpha[4];
#pragma unroll
        for (int i = 0; i < 4; i++) {
            float mnew = fmaxf(m[i], mloc[i]);
            alpha[i] = __expf(m[i] - mnew);
            m[i] = mnew;
        }

        // P = exp(S - m), row partial sums, write P to smem
        float rsum[4];
#pragma unroll
        for (int i = 0; i < 4; i++) {
            rsum[i] = 0.0f;
#pragma unroll
            for (int j = 0; j < 4; j++) {
                float p = __expf(s[i][j] - m[i]);
                rsum[i] += p;
                Ps[4 * tq + i][tk + 16 * j] = p;
            }
        }
#pragma unroll
        for (int o = 1; o < 16; o <<= 1) {
#pragma unroll
            for (int i = 0; i < 4; i++)
                rsum[i] += __shfl_xor_sync(0xffffffffu, rsum[i], o);
        }
#pragma unroll
        for (int i = 0; i < 4; i++) {
            l[i] = l[i] * alpha[i] + rsum[i];
#pragma unroll
            for (int j = 0; j < 4; j++) acc[i][j] *= alpha[i];
        }
        __syncthreads();   // Ps complete

        // O += P @ V
        for (int k = 0; k < 64; k++) {
            float pv[4], vv[4];
#pragma unroll
            for (int i = 0; i < 4; i++) pv[i] = Ps[4 * tq + i][k];
#pragma unroll
            for (int j = 0; j < 4; j++) vv[j] = Vs[k][tk + 16 * j];
#pragma unroll
            for (int i = 0; i < 4; i++)
#pragma unroll
                for (int j = 0; j < 4; j++)
                    acc[i][j] = fmaf(pv[i], vv[j], acc[i][j]);
        }
    }

    // epilogue: normalize and store [B,T,H,D] -> flattened [B,T,E]
#pragma unroll
    for (int i = 0; i < 4; i++) {
        const float inv = 1.0f / l[i];
        const int qg = q0 + 4 * tq + i;
        float* orow = out + ((size_t)b * T_ + qg) * E_ + h * D_;
#pragma unroll
        for (int j = 0; j < 4; j++) {
            orow[tk + 16 * j] = acc[i][j] * inv;
        }
    }
}

// ---------------------------------------------------------------------------
extern "C" void kernel_launch(void* const* d_in, const int* in_sizes, int n_in,
                              void* d_out, int out_size) {
    const float* x    = (const float*)d_in[0];
    const float* Wqkv = (const float*)d_in[1];
    const float* bqkv = (const float*)d_in[2];
    const float* Wout = (const float*)d_in[3];
    const float* bout = (const float*)d_in[4];
    float* out = (float*)d_out;

    float *qkv, *att;
    cudaGetSymbolAddress((void**)&qkv, g_qkv);
    cudaGetSymbolAddress((void**)&att, g_att);

    cudaFuncSetAttribute(flash_kernel,
                         cudaFuncAttributeMaxDynamicSharedMemorySize,
                         FLASH_SMEM);

    // 1) QKV projection: [B*T, E] @ [E, 3E] + bqkv
    {
        dim3 grid(THREE_E / BN, (B_ * T_) / BM);
        sgemm_bias<<<grid, 256>>>(B_ * T_, THREE_E, E_, x, Wqkv, bqkv, qkv);
    }
    // 2) Flash attention (causal + ALiBi)
    {
        dim3 grid(T_ / 64, B_ * H_);
        flash_kernel<<<grid, 256, FLASH_SMEM>>>(qkv, att);
    }
    // 3) Output projection: [B*T, E] @ [E, E] + bout
    {
        dim3 grid(E_ / BN, (B_ * T_) / BM);
        sgemm_bias<<<grid, 256>>>(B_ * T_, E_, E_, att, Wout, bout, out);
    }
}

// round 4
// speedup vs baseline: 2.1600x; 2.1600x over previous
#include <cuda_runtime.h>
#include <cstdint>

#define B_ 2
#define T_ 2048
#define E_ 2048
#define H_ 32
#define D_ 64
#define THREE_E (3 * E_)

// Scratch (no allocs allowed anywhere).
__device__ float g_qkv[(size_t)B_ * T_ * THREE_E];   // 96 MB
__device__ float g_att[(size_t)B_ * T_ * E_];        // 32 MB

// ---------------------------------------------------------------------------
// cp.async helpers
// ---------------------------------------------------------------------------
__device__ __forceinline__ uint32_t smem_u32(const void* p) {
    uint32_t a;
    asm("{ .reg .u64 t; cvta.to.shared.u64 t, %1; cvt.u32.u64 %0, t; }" : "=r"(a) : "l"(p));
    return a;
}
#define CP_ASYNC16(dst, src) \
    asm volatile("cp.async.cg.shared.global [%0], [%1], 16;" :: "r"(dst), "l"(src))
#define CP_COMMIT() asm volatile("cp.async.commit_group;" ::: "memory")
#define CP_WAIT1()  asm volatile("cp.async.wait_group 1;" ::: "memory")
#define CP_WAIT0()  asm volatile("cp.async.wait_group 0;" ::: "memory")

__device__ __forceinline__ uint32_t f2tf32(float x) {
    uint32_t r;
    asm("cvt.rna.tf32.f32 %0, %1;" : "=r"(r) : "f"(x));
    return r;
}

// m16n8k8 tf32 MMA (sm_80+ PTX; HMMA path on sm_100)
__device__ __forceinline__ void mma_tf32(float* c, const uint32_t* a, const uint32_t* b) {
    asm volatile(
        "mma.sync.aligned.m16n8k8.row.col.f32.tf32.tf32.f32 "
        "{%0,%1,%2,%3}, {%4,%5,%6,%7}, {%8,%9}, {%0,%1,%2,%3};"
        : "+f"(c[0]), "+f"(c[1]), "+f"(c[2]), "+f"(c[3])
        : "r"(a[0]), "r"(a[1]), "r"(a[2]), "r"(a[3]), "r"(b[0]), "r"(b[1]));
}

// ---------------------------------------------------------------------------
// tf32 tensor-core GEMM: C[M,N] = A[M,K] @ W[K,N] + bias[N]  (all row-major)
// CTA 128x128, BK=16, 256 threads (8 warps: 2 x 4), warp tile 64x32.
// Smem: As[128][20] (A[m][k], pad 20), Bs[16][136] (W[k][n], pad 136).
// Double-buffered cp.async.
// ---------------------------------------------------------------------------
#define BM 128
#define BN 128
#define BK 16
#define APAD 20
#define BPAD 136
#define NTHR 256

struct SmemTile {
    float As[BM][APAD];
    float Bs[BK][BPAD];
};

__global__ __launch_bounds__(NTHR)
void mma_gemm(int M, int N, int K,
              const float* __restrict__ A,
              const float* __restrict__ W,
              const float* __restrict__ bias,
              float* __restrict__ C) {
    __shared__ SmemTile sm[2];

    const int tid = threadIdx.x;
    const int wid = tid >> 5, lane = tid & 31;
    const int wm = wid >> 2, wn = wid & 3;        // 2 x 4 warp grid
    const int g = lane >> 2, t = lane & 3;

    const int m0 = blockIdx.y * BM;
    const int n0 = blockIdx.x * BN;

    const float* Ab = A + (size_t)m0 * K;
    const float* Wb = W + n0;

    float acc[4][4][4];
#pragma unroll
    for (int i = 0; i < 4; i++)
#pragma unroll
        for (int j = 0; j < 4; j++)
#pragma unroll
            for (int r = 0; r < 4; r++) acc[i][j][r] = 0.0f;

    const int NT = K / BK;

    // prefetch tile 0
    {
        const int k0 = 0;
#pragma unroll
        for (int it = 0; it < 2; it++) {
            int idx = tid + NTHR * it;
            int m = idx >> 2, kc = idx & 3;
            CP_ASYNC16(smem_u32(&sm[0].As[m][kc * 4]), Ab + (size_t)m * K + k0 + kc * 4);
        }
#pragma unroll
        for (int it = 0; it < 2; it++) {
            int idx = tid + NTHR * it;
            int k = idx >> 5, c = idx & 31;
            CP_ASYNC16(smem_u32(&sm[0].Bs[k][c * 4]), Wb + (size_t)(k0 + k) * N + c * 4);
        }
        CP_COMMIT();
    }

    int buf = 0;
    for (int kt = 0; kt < NT; kt++) {
        if (kt + 1 < NT) {
            const int k0 = (kt + 1) * BK;
            const int nb = buf ^ 1;
#pragma unroll
            for (int it = 0; it < 2; it++) {
                int idx = tid + NTHR * it;
                int m = idx >> 2, kc = idx & 3;
                CP_ASYNC16(smem_u32(&sm[nb].As[m][kc * 4]), Ab + (size_t)m * K + k0 + kc * 4);
            }
#pragma unroll
            for (int it = 0; it < 2; it++) {
                int idx = tid + NTHR * it;
                int k = idx >> 5, c = idx & 31;
                CP_ASYNC16(smem_u32(&sm[nb].Bs[k][c * 4]), Wb + (size_t)(k0 + k) * N + c * 4);
            }
            CP_COMMIT();
            CP_WAIT1();
        } else {
            CP_WAIT0();
        }
        __syncthreads();

        const SmemTile& S = sm[buf];
#pragma unroll
        for (int ks = 0; ks < 2; ks++) {
            const int kk = ks * 8;
            uint32_t af[4][4], bf[4][2];
#pragma unroll
            for (int mf = 0; mf < 4; mf++) {
                const int rA = wm * 64 + mf * 16;
                af[mf][0] = f2tf32(S.As[rA + g][kk + t]);
                af[mf][1] = f2tf32(S.As[rA + g + 8][kk + t]);
                af[mf][2] = f2tf32(S.As[rA + g][kk + t + 4]);
                af[mf][3] = f2tf32(S.As[rA + g + 8][kk + t + 4]);
            }
#pragma unroll
            for (int nf = 0; nf < 4; nf++) {
                const int cB = wn * 32 + nf * 8 + g;
                bf[nf][0] = f2tf32(S.Bs[kk + t][cB]);
                bf[nf][1] = f2tf32(S.Bs[kk + t + 4][cB]);
            }
#pragma unroll
            for (int mf = 0; mf < 4; mf++)
#pragma unroll
                for (int nf = 0; nf < 4; nf++)
                    mma_tf32(acc[mf][nf], af[mf], bf[nf]);
        }
        __syncthreads();
        buf ^= 1;
    }

    // epilogue: bias + store (float2 per half-fragment)
#pragma unroll
    for (int mf = 0; mf < 4; mf++) {
        const int row = m0 + wm * 64 + mf * 16 + g;
#pragma unroll
        for (int nf = 0; nf < 4; nf++) {
            const int col = n0 + wn * 32 + nf * 8 + 2 * t;
            const float b0 = bias[col], b1 = bias[col + 1];
            float2 v0 = { acc[mf][nf][0] + b0, acc[mf][nf][1] + b1 };
            float2 v1 = { acc[mf][nf][2] + b0, acc[mf][nf][3] + b1 };
            *(float2*)(C + (size_t)row * N + col) = v0;
            *(float2*)(C + (size_t)(row + 8) * N + col) = v1;
        }
    }
}

// ---------------------------------------------------------------------------
// Flash attention fp32 with ALiBi + causal mask (round-1 proven version).
// ---------------------------------------------------------------------------
#define FPAD 65
#define FLASH_SMEM (4 * 64 * FPAD * (int)sizeof(float))

__global__ __launch_bounds__(256, 3)
void flash_kernel(const float* __restrict__ qkv, float* __restrict__ out) {
    extern __shared__ float smem[];
    float (*Qs)[FPAD] = (float(*)[FPAD])(smem);
    float (*Ks)[FPAD] = (float(*)[FPAD])(smem + 64 * FPAD);
    float (*Vs)[FPAD] = (float(*)[FPAD])(smem + 2 * 64 * FPAD);
    float (*Ps)[FPAD] = (float(*)[FPAD])(smem + 3 * 64 * FPAD);

    const int tid = threadIdx.x;
    const int tk = tid & 15;
    const int tq = tid >> 4;

    const int qb = blockIdx.x;
    const int bh = blockIdx.y;
    const int b = bh >> 5;
    const int h = bh & 31;

    const float slope = exp2f(-0.25f * (float)(h + 1));
    const float scale = 8.0f / (float)D_;

    const size_t base = (size_t)b * T_ * THREE_E;
    const float* Qg = qkv + base + (size_t)h * D_;
    const float* Kg = qkv + base + E_ + (size_t)h * D_;
    const float* Vg = qkv + base + 2 * E_ + (size_t)h * D_;

    const int q0 = qb * 64;

    for (int i = tid; i < 64 * 64; i += 256) {
        int r = i >> 6, c = i & 63;
        Qs[r][c] = Qg[(size_t)(q0 + r) * THREE_E + c] * scale;
    }

    float m[4], l[4], acc[4][4];
#pragma unroll
    for (int i = 0; i < 4; i++) {
        m[i] = -1e30f; l[i] = 0.0f;
#pragma unroll
        for (int j = 0; j < 4; j++) acc[i][j] = 0.0f;
    }

    const int nkb = qb + 1;
    for (int kb = 0; kb < nkb; kb++) {
        __syncthreads();
        for (int i = tid; i < 64 * 64; i += 256) {
            int r = i >> 6, c = i & 63;
            size_t goff = (size_t)(kb * 64 + r) * THREE_E + c;
            Ks[r][c] = Kg[goff];
            Vs[r][c] = Vg[goff];
        }
        __syncthreads();

        float s[4][4];
#pragma unroll
        for (int i = 0; i < 4; i++)
#pragma unroll
            for (int j = 0; j < 4; j++) s[i][j] = 0.0f;

        for (int d = 0; d < 64; d++) {
            float qv[4], kv[4];
#pragma unroll
            for (int i = 0; i < 4; i++) qv[i] = Qs[4 * tq + i][d];
#pragma unroll
            for (int j = 0; j < 4; j++) kv[j] = Ks[tk + 16 * j][d];
#pragma unroll
            for (int i = 0; i < 4; i++)
#pragma unroll
                for (int j = 0; j < 4; j++)
                    s[i][j] = fmaf(qv[i], kv[j], s[i][j]);
        }

#pragma unroll
        for (int i = 0; i < 4; i++) {
            const int qg = q0 + 4 * tq + i;
#pragma unroll
            for (int j = 0; j < 4; j++) {
                const int kg = kb * 64 + tk + 16 * j;
                s[i][j] = (kg > qg) ? -1e30f : s[i][j] + slope * (float)(kg - qg);
            }
        }

        float mloc[4];
#pragma unroll
        for (int i = 0; i < 4; i++)
            mloc[i] = fmaxf(fmaxf(s[i][0], s[i][1]), fmaxf(s[i][2], s[i][3]));
#pragma unroll
        for (int o = 1; o < 16; o <<= 1) {
#pragma unroll
            for (int i = 0; i < 4; i++)
                mloc[i] = fmaxf(mloc[i], __shfl_xor_sync(0xffffffffu, mloc[i], o));
        }

        float alpha[4];
#pragma unroll
        for (int i = 0; i < 4; i++) {
            float mnew = fmaxf(m[i], mloc[i]);
            alpha[i] = __expf(m[i] - mnew);
            m[i] = mnew;
        }

        float rsum[4];
#pragma unroll
        for (int i = 0; i < 4; i++) {
            rsum[i] = 0.0f;
#pragma unroll
            for (int j = 0; j < 4; j++) {
                float p = __expf(s[i][j] - m[i]);
                rsum[i] += p;
                Ps[4 * tq + i][tk + 16 * j] = p;
            }
        }
#pragma unroll
        for (int o = 1; o < 16; o <<= 1) {
#pragma unroll
            for (int i = 0; i < 4; i++)
                rsum[i] += __shfl_xor_sync(0xffffffffu, rsum[i], o);
        }
#pragma unroll
        for (int i = 0; i < 4; i++) {
            l[i] = l[i] * alpha[i] + rsum[i];
#pragma unroll
            for (int j = 0; j < 4; j++) acc[i][j] *= alpha[i];
        }
        __syncthreads();

        for (int k = 0; k < 64; k++) {
            float pv[4], vv[4];
#pragma unroll
            for (int i = 0; i < 4; i++) pv[i] = Ps[4 * tq + i][k];
#pragma unroll
            for (int j = 0; j < 4; j++) vv[j] = Vs[k][tk + 16 * j];
#pragma unroll
            for (int i = 0; i < 4; i++)
#pragma unroll
                for (int j = 0; j < 4; j++)
                    acc[i][j] = fmaf(pv[i], vv[j], acc[i][j]);
        }
    }

#pragma unroll
    for (int i = 0; i < 4; i++) {
        const float inv = 1.0f / l[i];
        const int qg = q0 + 4 * tq + i;
        float* orow = out + ((size_t)b * T_ + qg) * E_ + h * D_;
#pragma unroll
        for (int j = 0; j < 4; j++) orow[tk + 16 * j] = acc[i][j] * inv;
    }
}

// ---------------------------------------------------------------------------
extern "C" void kernel_launch(void* const* d_in, const int* in_sizes, int n_in,
                              void* d_out, int out_size) {
    const float* x    = (const float*)d_in[0];
    const float* Wqkv = (const float*)d_in[1];
    const float* bqkv = (const float*)d_in[2];
    const float* Wout = (const float*)d_in[3];
    const float* bout = (const float*)d_in[4];
    float* out = (float*)d_out;

    float *qkv, *att;
    cudaGetSymbolAddress((void**)&qkv, g_qkv);
    cudaGetSymbolAddress((void**)&att, g_att);

    cudaFuncSetAttribute(flash_kernel, cudaFuncAttributeMaxDynamicSharedMemorySize, FLASH_SMEM);

    // 1) QKV projection (tf32 tensor cores)
    mma_gemm<<<dim3(THREE_E / BN, (B_ * T_) / BM), NTHR>>>(
        B_ * T_, THREE_E, E_, x, Wqkv, bqkv, qkv);

    // 2) Flash attention (causal + ALiBi)
    flash_kernel<<<dim3(T_ / 64, B_ * H_), 256, FLASH_SMEM>>>(qkv, att);

    // 3) Output projection (tf32 tensor cores)
    mma_gemm<<<dim3(E_ / BN, (B_ * T_) / BM), NTHR>>>(
        B_ * T_, E_, E_, att, Wout, bout, out);
}

// round 5
// speedup vs baseline: 2.9757x; 1.3776x over previous
#include <cuda_runtime.h>
#include <cuda_bf16.h>
#include <cstdint>

#define B_ 2
#define T_ 2048
#define E_ 2048
#define H_ 32
#define D_ 64
#define THREE_E (3 * E_)

// Scratch (no allocs allowed anywhere).
__device__ float g_qkv[(size_t)B_ * T_ * THREE_E];   // 96 MB
__device__ float g_att[(size_t)B_ * T_ * E_];        // 32 MB

// ---------------------------------------------------------------------------
// helpers
// ---------------------------------------------------------------------------
__device__ __forceinline__ uint32_t smem_u32(const void* p) {
    uint32_t a;
    asm("{ .reg .u64 t; cvta.to.shared.u64 t, %1; cvt.u32.u64 %0, t; }" : "=r"(a) : "l"(p));
    return a;
}
#define CP_ASYNC16(dst, src) \
    asm volatile("cp.async.cg.shared.global [%0], [%1], 16;" :: "r"(dst), "l"(src))
#define CP_COMMIT() asm volatile("cp.async.commit_group;" ::: "memory")
#define CP_WAIT1()  asm volatile("cp.async.wait_group 1;" ::: "memory")
#define CP_WAIT0()  asm volatile("cp.async.wait_group 0;" ::: "memory")

__device__ __forceinline__ uint32_t f2tf32(float x) {
    uint32_t r;
    asm("cvt.rna.tf32.f32 %0, %1;" : "=r"(r) : "f"(x));
    return r;
}

// m16n8k8 tf32 MMA
__device__ __forceinline__ void mma_tf32(float* c, const uint32_t* a, const uint32_t* b) {
    asm volatile(
        "mma.sync.aligned.m16n8k8.row.col.f32.tf32.tf32.f32 "
        "{%0,%1,%2,%3}, {%4,%5,%6,%7}, {%8,%9}, {%0,%1,%2,%3};"
        : "+f"(c[0]), "+f"(c[1]), "+f"(c[2]), "+f"(c[3])
        : "r"(a[0]), "r"(a[1]), "r"(a[2]), "r"(a[3]), "r"(b[0]), "r"(b[1]));
}

// m16n8k16 bf16 MMA
__device__ __forceinline__ void mma_bf16(float* c, const uint32_t* a, uint32_t b0, uint32_t b1) {
    asm volatile(
        "mma.sync.aligned.m16n8k16.row.col.f32.bf16.bf16.f32 "
        "{%0,%1,%2,%3}, {%4,%5,%6,%7}, {%8,%9}, {%0,%1,%2,%3};"
        : "+f"(c[0]), "+f"(c[1]), "+f"(c[2]), "+f"(c[3])
        : "r"(a[0]), "r"(a[1]), "r"(a[2]), "r"(a[3]), "r"(b0), "r"(b1));
}

// split (x,y) into hi/lo bf16x2 words: x -> low 16 bits, y -> high 16 bits
__device__ __forceinline__ void split2(float x, float y, uint32_t& hi, uint32_t& lo) {
    __nv_bfloat16 hx = __float2bfloat16(x);
    __nv_bfloat16 hy = __float2bfloat16(y);
    __nv_bfloat16 lx = __float2bfloat16(x - __bfloat162float(hx));
    __nv_bfloat16 ly = __float2bfloat16(y - __bfloat162float(hy));
    hi = ((uint32_t)__bfloat16_as_ushort(hy) << 16) | __bfloat16_as_ushort(hx);
    lo = ((uint32_t)__bfloat16_as_ushort(ly) << 16) | __bfloat16_as_ushort(lx);
}

// ---------------------------------------------------------------------------
// tf32 tensor-core GEMM (unchanged, round-4 proven): C = A @ W + bias
// ---------------------------------------------------------------------------
#define BM 128
#define BN 128
#define BK 16
#define APAD 20
#define BPAD 136
#define NTHR 256

struct SmemTile {
    float As[BM][APAD];
    float Bs[BK][BPAD];
};

__global__ __launch_bounds__(NTHR)
void mma_gemm(int M, int N, int K,
              const float* __restrict__ A,
              const float* __restrict__ W,
              const float* __restrict__ bias,
              float* __restrict__ C) {
    __shared__ SmemTile sm[2];

    const int tid = threadIdx.x;
    const int wid = tid >> 5, lane = tid & 31;
    const int wm = wid >> 2, wn = wid & 3;
    const int g = lane >> 2, t = lane & 3;

    const int m0 = blockIdx.y * BM;
    const int n0 = blockIdx.x * BN;

    const float* Ab = A + (size_t)m0 * K;
    const float* Wb = W + n0;

    float acc[4][4][4];
#pragma unroll
    for (int i = 0; i < 4; i++)
#pragma unroll
        for (int j = 0; j < 4; j++)
#pragma unroll
            for (int r = 0; r < 4; r++) acc[i][j][r] = 0.0f;

    const int NT = K / BK;

    {
#pragma unroll
        for (int it = 0; it < 2; it++) {
            int idx = tid + NTHR * it;
            int m = idx >> 2, kc = idx & 3;
            CP_ASYNC16(smem_u32(&sm[0].As[m][kc * 4]), Ab + (size_t)m * K + kc * 4);
        }
#pragma unroll
        for (int it = 0; it < 2; it++) {
            int idx = tid + NTHR * it;
            int k = idx >> 5, c = idx & 31;
            CP_ASYNC16(smem_u32(&sm[0].Bs[k][c * 4]), Wb + (size_t)k * N + c * 4);
        }
        CP_COMMIT();
    }

    int buf = 0;
    for (int kt = 0; kt < NT; kt++) {
        if (kt + 1 < NT) {
            const int k0 = (kt + 1) * BK;
            const int nb = buf ^ 1;
#pragma unroll
            for (int it = 0; it < 2; it++) {
                int idx = tid + NTHR * it;
                int m = idx >> 2, kc = idx & 3;
                CP_ASYNC16(smem_u32(&sm[nb].As[m][kc * 4]), Ab + (size_t)m * K + k0 + kc * 4);
            }
#pragma unroll
            for (int it = 0; it < 2; it++) {
                int idx = tid + NTHR * it;
                int k = idx >> 5, c = idx & 31;
                CP_ASYNC16(smem_u32(&sm[nb].Bs[k][c * 4]), Wb + (size_t)(k0 + k) * N + c * 4);
            }
            CP_COMMIT();
            CP_WAIT1();
        } else {
            CP_WAIT0();
        }
        __syncthreads();

        const SmemTile& S = sm[buf];
#pragma unroll
        for (int ks = 0; ks < 2; ks++) {
            const int kk = ks * 8;
            uint32_t af[4][4], bf[4][2];
#pragma unroll
            for (int mf = 0; mf < 4; mf++) {
                const int rA = wm * 64 + mf * 16;
                af[mf][0] = f2tf32(S.As[rA + g][kk + t]);
                af[mf][1] = f2tf32(S.As[rA + g + 8][kk + t]);
                af[mf][2] = f2tf32(S.As[rA + g][kk + t + 4]);
                af[mf][3] = f2tf32(S.As[rA + g + 8][kk + t + 4]);
            }
#pragma unroll
            for (int nf = 0; nf < 4; nf++) {
                const int cB = wn * 32 + nf * 8 + g;
                bf[nf][0] = f2tf32(S.Bs[kk + t][cB]);
                bf[nf][1] = f2tf32(S.Bs[kk + t + 4][cB]);
            }
#pragma unroll
            for (int mf = 0; mf < 4; mf++)
#pragma unroll
                for (int nf = 0; nf < 4; nf++)
                    mma_tf32(acc[mf][nf], af[mf], bf[nf]);
        }
        __syncthreads();
        buf ^= 1;
    }

#pragma unroll
    for (int mf = 0; mf < 4; mf++) {
        const int row = m0 + wm * 64 + mf * 16 + g;
#pragma unroll
        for (int nf = 0; nf < 4; nf++) {
            const int col = n0 + wn * 32 + nf * 8 + 2 * t;
            const float b0 = bias[col], b1 = bias[col + 1];
            float2 v0 = { acc[mf][nf][0] + b0, acc[mf][nf][1] + b1 };
            float2 v1 = { acc[mf][nf][2] + b0, acc[mf][nf][3] + b1 };
            *(float2*)(C + (size_t)row * N + col) = v0;
            *(float2*)(C + (size_t)(row + 8) * N + col) = v1;
        }
    }
}

// ---------------------------------------------------------------------------
// Tensor-core flash attention: bf16 3-term split, ALiBi + causal.
// Grid (T/64, B*H), 128 threads (4 warps x 16 q-rows).
// Smem: QH,QL,KH,KL,VH,VL each [64][36] u32 (bf16x2 pairs, stride 36 -> the
// fragment bank is 4g+t: conflict-free). V stored k-transposed (pairs along k).
// ---------------------------------------------------------------------------
#define FST 36
#define FARR (64 * FST)
#define FLASH_SMEM (6 * FARR * 4)

__global__ __launch_bounds__(128)
void flash_mma(const float* __restrict__ qkv, float* __restrict__ out) {
    extern __shared__ uint32_t fsm[];
    uint32_t* QH = fsm;
    uint32_t* QL = QH + FARR;
    uint32_t* KH = QL + FARR;
    uint32_t* KL = KH + FARR;
    uint32_t* VH = KL + FARR;
    uint32_t* VL = VH + FARR;

    const int tid = threadIdx.x;
    const int wid = tid >> 5, lane = tid & 31;
    const int g = lane >> 2, t = lane & 3;

    const int qb = blockIdx.x;
    const int bh = blockIdx.y;
    const int b = bh >> 5;
    const int h = bh & 31;

    const float slope = exp2f(-0.25f * (float)(h + 1));
    const float scale = 8.0f / (float)D_;

    const size_t base = (size_t)b * T_ * THREE_E;
    const float* Qg = qkv + base + (size_t)h * D_;
    const float* Kg = qkv + base + E_ + (size_t)h * D_;
    const float* Vg = qkv + base + 2 * E_ + (size_t)h * D_;

    const int q0 = qb * 64;

    // Q tile: scale, split, pack pairs along d
    for (int i = tid; i < 64 * 32; i += 128) {
        int r = i >> 5, dp = i & 31;
        const float* p = Qg + (size_t)(q0 + r) * THREE_E + dp * 2;
        uint32_t hi, lo;
        split2(p[0] * scale, p[1] * scale, hi, lo);
        QH[r * FST + dp] = hi;
        QL[r * FST + dp] = lo;
    }

    float o[8][4];
#pragma unroll
    for (int nf = 0; nf < 8; nf++)
#pragma unroll
        for (int r = 0; r < 4; r++) o[nf][r] = 0.0f;
    float m0 = -1e30f, m1 = -1e30f, l0 = 0.0f, l1 = 0.0f;

    const int rW = wid * 16;              // warp's q-row base (local)
    const int qg0 = q0 + rW + g;          // global q rows handled by this lane
    const int qg1 = qg0 + 8;

    for (int kb = 0; kb <= qb; kb++) {
        __syncthreads();
        // K tile: pairs along d
        for (int i = tid; i < 64 * 32; i += 128) {
            int r = i >> 5, dp = i & 31;
            const float* p = Kg + (size_t)(kb * 64 + r) * THREE_E + dp * 2;
            uint32_t hi, lo;
            split2(p[0], p[1], hi, lo);
            KH[r * FST + dp] = hi;
            KL[r * FST + dp] = lo;
        }
        // V tile transposed: VH[d][kpair], pairs along k
        for (int i = tid; i < 64 * 32; i += 128) {
            int d = i & 63, kp = i >> 6;
            const float* p = Vg + (size_t)(kb * 64 + kp * 2) * THREE_E + d;
            uint32_t hi, lo;
            split2(p[0], p[THREE_E], hi, lo);
            VH[d * FST + kp] = hi;
            VL[d * FST + kp] = lo;
        }
        __syncthreads();

        // ---- S = Q @ K^T (3-term bf16) ----
        float c[8][4];
#pragma unroll
        for (int nf = 0; nf < 8; nf++)
#pragma unroll
            for (int r = 0; r < 4; r++) c[nf][r] = 0.0f;

#pragma unroll
        for (int kt = 0; kt < 4; kt++) {
            uint32_t ah[4], al[4];
            ah[0] = QH[(rW + g) * FST + kt * 8 + t];
            ah[1] = QH[(rW + g + 8) * FST + kt * 8 + t];
            ah[2] = QH[(rW + g) * FST + kt * 8 + t + 4];
            ah[3] = QH[(rW + g + 8) * FST + kt * 8 + t + 4];
            al[0] = QL[(rW + g) * FST + kt * 8 + t];
            al[1] = QL[(rW + g + 8) * FST + kt * 8 + t];
            al[2] = QL[(rW + g) * FST + kt * 8 + t + 4];
            al[3] = QL[(rW + g + 8) * FST + kt * 8 + t + 4];
#pragma unroll
            for (int nf = 0; nf < 8; nf++) {
                const int rB = (8 * nf + g) * FST + kt * 8 + t;
                uint32_t bh0 = KH[rB], bh1 = KH[rB + 4];
                uint32_t bl0 = KL[rB], bl1 = KL[rB + 4];
                mma_bf16(c[nf], ah, bh0, bh1);
                mma_bf16(c[nf], al, bh0, bh1);
                mma_bf16(c[nf], ah, bl0, bl1);
            }
        }

        // ---- mask + ALiBi ----
#pragma unroll
        for (int nf = 0; nf < 8; nf++) {
            const int col0 = kb * 64 + 8 * nf + 2 * t;
            const int col1 = col0 + 1;
            c[nf][0] = (col0 > qg0) ? -1e30f : c[nf][0] + slope * (float)(col0 - qg0);
            c[nf][1] = (col1 > qg0) ? -1e30f : c[nf][1] + slope * (float)(col1 - qg0);
            c[nf][2] = (col0 > qg1) ? -1e30f : c[nf][2] + slope * (float)(col0 - qg1);
            c[nf][3] = (col1 > qg1) ? -1e30f : c[nf][3] + slope * (float)(col1 - qg1);
        }

        // ---- online softmax ----
        float mx0 = -1e30f, mx1 = -1e30f;
#pragma unroll
        for (int nf = 0; nf < 8; nf++) {
            mx0 = fmaxf(mx0, fmaxf(c[nf][0], c[nf][1]));
            mx1 = fmaxf(mx1, fmaxf(c[nf][2], c[nf][3]));
        }
        mx0 = fmaxf(mx0, __shfl_xor_sync(0xffffffffu, mx0, 1));
        mx0 = fmaxf(mx0, __shfl_xor_sync(0xffffffffu, mx0, 2));
        mx1 = fmaxf(mx1, __shfl_xor_sync(0xffffffffu, mx1, 1));
        mx1 = fmaxf(mx1, __shfl_xor_sync(0xffffffffu, mx1, 2));

        const float mn0 = fmaxf(m0, mx0), mn1 = fmaxf(m1, mx1);
        const float alpha0 = __expf(m0 - mn0), alpha1 = __expf(m1 - mn1);
        m0 = mn0; m1 = mn1;

        float s0 = 0.0f, s1 = 0.0f;
#pragma unroll
        for (int nf = 0; nf < 8; nf++) {
            c[nf][0] = __expf(c[nf][0] - m0);
            c[nf][1] = __expf(c[nf][1] - m0);
            c[nf][2] = __expf(c[nf][2] - m1);
            c[nf][3] = __expf(c[nf][3] - m1);
            s0 += c[nf][0] + c[nf][1];
            s1 += c[nf][2] + c[nf][3];
        }
        s0 += __shfl_xor_sync(0xffffffffu, s0, 1);
        s0 += __shfl_xor_sync(0xffffffffu, s0, 2);
        s1 += __shfl_xor_sync(0xffffffffu, s1, 1);
        s1 += __shfl_xor_sync(0xffffffffu, s1, 2);
        l0 = l0 * alpha0 + s0;
        l1 = l1 * alpha1 + s1;

        // pack P into A-fragments (c-layout == a-layout, no shuffles)
        uint32_t pah[4][4], pal[4][4];
#pragma unroll
        for (int kt = 0; kt < 4; kt++) {
            split2(c[2 * kt][0],     c[2 * kt][1],     pah[kt][0], pal[kt][0]);
            split2(c[2 * kt][2],     c[2 * kt][3],     pah[kt][1], pal[kt][1]);
            split2(c[2 * kt + 1][0], c[2 * kt + 1][1], pah[kt][2], pal[kt][2]);
            split2(c[2 * kt + 1][2], c[2 * kt + 1][3], pah[kt][3], pal[kt][3]);
        }

#pragma unroll
        for (int nf = 0; nf < 8; nf++) {
            o[nf][0] *= alpha0; o[nf][1] *= alpha0;
            o[nf][2] *= alpha1; o[nf][3] *= alpha1;
        }

        // ---- O += P @ V (3-term bf16) ----
#pragma unroll
        for (int kt = 0; kt < 4; kt++) {
#pragma unroll
            for (int nf = 0; nf < 8; nf++) {
                const int rB = (8 * nf + g) * FST + kt * 8 + t;
                uint32_t bh0 = VH[rB], bh1 = VH[rB + 4];
                uint32_t bl0 = VL[rB], bl1 = VL[rB + 4];
                mma_bf16(o[nf], pah[kt], bh0, bh1);
                mma_bf16(o[nf], pal[kt], bh0, bh1);
                mma_bf16(o[nf], pah[kt], bl0, bl1);
            }
        }
    }

    // epilogue
    const float inv0 = 1.0f / l0, inv1 = 1.0f / l1;
    float* o0 = out + ((size_t)b * T_ + qg0) * E_ + h * D_;
    float* o1 = out + ((size_t)b * T_ + qg1) * E_ + h * D_;
#pragma unroll
    for (int nf = 0; nf < 8; nf++) {
        const int col = 8 * nf + 2 * t;
        float2 v0 = { o[nf][0] * inv0, o[nf][1] * inv0 };
        float2 v1 = { o[nf][2] * inv1, o[nf][3] * inv1 };
        *(float2*)(o0 + col) = v0;
        *(float2*)(o1 + col) = v1;
    }
}

// ---------------------------------------------------------------------------
extern "C" void kernel_launch(void* const* d_in, const int* in_sizes, int n_in,
                              void* d_out, int out_size) {
    const float* x    = (const float*)d_in[0];
    const float* Wqkv = (const float*)d_in[1];
    const float* bqkv = (const float*)d_in[2];
    const float* Wout = (const float*)d_in[3];
    const float* bout = (const float*)d_in[4];
    float* out = (float*)d_out;

    float *qkv, *att;
    cudaGetSymbolAddress((void**)&qkv, g_qkv);
    cudaGetSymbolAddress((void**)&att, g_att);

    cudaFuncSetAttribute(flash_mma, cudaFuncAttributeMaxDynamicSharedMemorySize, FLASH_SMEM);

    // 1) QKV projection (tf32 tensor cores)
    mma_gemm<<<dim3(THREE_E / BN, (B_ * T_) / BM), NTHR>>>(
        B_ * T_, THREE_E, E_, x, Wqkv, bqkv, qkv);

    // 2) Flash attention (bf16 3-term tensor cores)
    flash_mma<<<dim3(T_ / 64, B_ * H_), 128, FLASH_SMEM>>>(qkv, att);

    // 3) Output projection (tf32 tensor cores)
    mma_gemm<<<dim3(E_ / BN, (B_ * T_) / BM), NTHR>>>(
        B_ * T_, E_, E_, att, Wout, bout, out);
}

// round 6
// speedup vs baseline: 3.0042x; 1.0096x over previous
#include <cuda_runtime.h>
#include <cuda_bf16.h>
#include <cstdint>

#define B_ 2
#define T_ 2048
#define E_ 2048
#define H_ 32
#define D_ 64
#define THREE_E (3 * E_)

// Scratch (no allocs allowed anywhere).
__device__ float g_qkv[(size_t)B_ * T_ * THREE_E];   // 96 MB
__device__ float g_att[(size_t)B_ * T_ * E_];        // 32 MB (tf32-rounded by flash epilogue)
__device__ float g_rx[(size_t)B_ * T_ * E_];         // 32 MB (x rounded to tf32)
__device__ float g_rwq[(size_t)E_ * THREE_E];        // 48 MB (Wqkv rounded)
__device__ float g_rwo[(size_t)E_ * E_];             // 16 MB (Wout rounded)

// ---------------------------------------------------------------------------
// helpers
// ---------------------------------------------------------------------------
__device__ __forceinline__ uint32_t smem_u32(const void* p) {
    uint32_t a;
    asm("{ .reg .u64 t; cvta.to.shared.u64 t, %1; cvt.u32.u64 %0, t; }" : "=r"(a) : "l"(p));
    return a;
}
#define CP_ASYNC16(dst, src) \
    asm volatile("cp.async.cg.shared.global [%0], [%1], 16;" :: "r"(dst), "l"(src))
#define CP_COMMIT() asm volatile("cp.async.commit_group;" ::: "memory")
#define CP_WAIT1()  asm volatile("cp.async.wait_group 1;" ::: "memory")
#define CP_WAIT0()  asm volatile("cp.async.wait_group 0;" ::: "memory")

__device__ __forceinline__ uint32_t f2tf32(float x) {
    uint32_t r;
    asm("cvt.rna.tf32.f32 %0, %1;" : "=r"(r) : "f"(x));
    return r;
}

// m16n8k8 tf32 MMA (operands pre-rounded to tf32 bit patterns)
__device__ __forceinline__ void mma_tf32(float* c, const uint32_t* a, const uint32_t* b) {
    asm volatile(
        "mma.sync.aligned.m16n8k8.row.col.f32.tf32.tf32.f32 "
        "{%0,%1,%2,%3}, {%4,%5,%6,%7}, {%8,%9}, {%0,%1,%2,%3};"
        : "+f"(c[0]), "+f"(c[1]), "+f"(c[2]), "+f"(c[3])
        : "r"(a[0]), "r"(a[1]), "r"(a[2]), "r"(a[3]), "r"(b[0]), "r"(b[1]));
}

// m16n8k16 bf16 MMA
__device__ __forceinline__ void mma_bf16(float* c, const uint32_t* a, uint32_t b0, uint32_t b1) {
    asm volatile(
        "mma.sync.aligned.m16n8k16.row.col.f32.bf16.bf16.f32 "
        "{%0,%1,%2,%3}, {%4,%5,%6,%7}, {%8,%9}, {%0,%1,%2,%3};"
        : "+f"(c[0]), "+f"(c[1]), "+f"(c[2]), "+f"(c[3])
        : "r"(a[0]), "r"(a[1]), "r"(a[2]), "r"(a[3]), "r"(b0), "r"(b1));
}

// split (x,y) into hi/lo bf16x2 words
__device__ __forceinline__ void split2(float x, float y, uint32_t& hi, uint32_t& lo) {
    __nv_bfloat16 hx = __float2bfloat16(x);
    __nv_bfloat16 hy = __float2bfloat16(y);
    __nv_bfloat16 lx = __float2bfloat16(x - __bfloat162float(hx));
    __nv_bfloat16 ly = __float2bfloat16(y - __bfloat162float(hy));
    hi = ((uint32_t)__bfloat16_as_ushort(hy) << 16) | __bfloat16_as_ushort(hx);
    lo = ((uint32_t)__bfloat16_as_ushort(ly) << 16) | __bfloat16_as_ushort(lx);
}

// ---------------------------------------------------------------------------
// Pre-round fp32 -> tf32 bit patterns (elementwise, float4)
// ---------------------------------------------------------------------------
__global__ void round_tf32(const float4* __restrict__ in, float4* __restrict__ out, int n4) {
    int i = blockIdx.x * blockDim.x + threadIdx.x;
    if (i < n4) {
        float4 v = in[i];
        float4 r;
        r.x = __uint_as_float(f2tf32(v.x));
        r.y = __uint_as_float(f2tf32(v.y));
        r.z = __uint_as_float(f2tf32(v.z));
        r.w = __uint_as_float(f2tf32(v.w));
        out[i] = r;
    }
}

// ---------------------------------------------------------------------------
// tf32 tensor-core GEMM: C = A @ W + bias. A and W PRE-ROUNDED to tf32 bits.
// CTA 128x128, BK=16, 256 threads (8 warps: 2 x 4), warp tile 64x32.
// ---------------------------------------------------------------------------
#define BM 128
#define BN 128
#define BK 16
#define APAD 20
#define BPAD 136
#define NTHR 256

struct SmemTile {
    float As[BM][APAD];
    float Bs[BK][BPAD];
};

__global__ __launch_bounds__(NTHR)
void mma_gemm(int M, int N, int K,
              const float* __restrict__ A,
              const float* __restrict__ W,
              const float* __restrict__ bias,
              float* __restrict__ C) {
    __shared__ SmemTile sm[2];

    const int tid = threadIdx.x;
    const int wid = tid >> 5, lane = tid & 31;
    const int wm = wid >> 2, wn = wid & 3;
    const int g = lane >> 2, t = lane & 3;

    const int m0 = blockIdx.y * BM;
    const int n0 = blockIdx.x * BN;

    const float* Ab = A + (size_t)m0 * K;
    const float* Wb = W + n0;

    float acc[4][4][4];
#pragma unroll
    for (int i = 0; i < 4; i++)
#pragma unroll
        for (int j = 0; j < 4; j++)
#pragma unroll
            for (int r = 0; r < 4; r++) acc[i][j][r] = 0.0f;

    const int NT = K / BK;

    {
#pragma unroll
        for (int it = 0; it < 2; it++) {
            int idx = tid + NTHR * it;
            int m = idx >> 2, kc = idx & 3;
            CP_ASYNC16(smem_u32(&sm[0].As[m][kc * 4]), Ab + (size_t)m * K + kc * 4);
        }
#pragma unroll
        for (int it = 0; it < 2; it++) {
            int idx = tid + NTHR * it;
            int k = idx >> 5, c = idx & 31;
            CP_ASYNC16(smem_u32(&sm[0].Bs[k][c * 4]), Wb + (size_t)k * N + c * 4);
        }
        CP_COMMIT();
    }

    int buf = 0;
    for (int kt = 0; kt < NT; kt++) {
        if (kt + 1 < NT) {
            const int k0 = (kt + 1) * BK;
            const int nb = buf ^ 1;
#pragma unroll
            for (int it = 0; it < 2; it++) {
                int idx = tid + NTHR * it;
                int m = idx >> 2, kc = idx & 3;
                CP_ASYNC16(smem_u32(&sm[nb].As[m][kc * 4]), Ab + (size_t)m * K + k0 + kc * 4);
            }
#pragma unroll
            for (int it = 0; it < 2; it++) {
                int idx = tid + NTHR * it;
                int k = idx >> 5, c = idx & 31;
                CP_ASYNC16(smem_u32(&sm[nb].Bs[k][c * 4]), Wb + (size_t)(k0 + k) * N + c * 4);
            }
            CP_COMMIT();
            CP_WAIT1();
        } else {
            CP_WAIT0();
        }
        __syncthreads();

        const SmemTile& S = sm[buf];
#pragma unroll
        for (int ks = 0; ks < 2; ks++) {
            const int kk = ks * 8;
            uint32_t af[4][4], bf[4][2];
#pragma unroll
            for (int mf = 0; mf < 4; mf++) {
                const int rA = wm * 64 + mf * 16;
                af[mf][0] = __float_as_uint(S.As[rA + g][kk + t]);
                af[mf][1] = __float_as_uint(S.As[rA + g + 8][kk + t]);
                af[mf][2] = __float_as_uint(S.As[rA + g][kk + t + 4]);
                af[mf][3] = __float_as_uint(S.As[rA + g + 8][kk + t + 4]);
            }
#pragma unroll
            for (int nf = 0; nf < 4; nf++) {
                const int cB = wn * 32 + nf * 8 + g;
                bf[nf][0] = __float_as_uint(S.Bs[kk + t][cB]);
                bf[nf][1] = __float_as_uint(S.Bs[kk + t + 4][cB]);
            }
#pragma unroll
            for (int mf = 0; mf < 4; mf++)
#pragma unroll
                for (int nf = 0; nf < 4; nf++)
                    mma_tf32(acc[mf][nf], af[mf], bf[nf]);
        }
        __syncthreads();
        buf ^= 1;
    }

#pragma unroll
    for (int mf = 0; mf < 4; mf++) {
        const int row = m0 + wm * 64 + mf * 16 + g;
#pragma unroll
        for (int nf = 0; nf < 4; nf++) {
            const int col = n0 + wn * 32 + nf * 8 + 2 * t;
            const float b0 = bias[col], b1 = bias[col + 1];
            float2 v0 = { acc[mf][nf][0] + b0, acc[mf][nf][1] + b1 };
            float2 v1 = { acc[mf][nf][2] + b0, acc[mf][nf][3] + b1 };
            *(float2*)(C + (size_t)row * N + col) = v0;
            *(float2*)(C + (size_t)(row + 8) * N + col) = v1;
        }
    }
}

// ---------------------------------------------------------------------------
// Tensor-core flash attention: bf16 3-term split, ALiBi + causal.
// Epilogue stores tf32-ROUNDED values (feeds the pre-rounded out-proj GEMM).
// ---------------------------------------------------------------------------
#define FST 36
#define FARR (64 * FST)
#define FLASH_SMEM (6 * FARR * 4)

__global__ __launch_bounds__(128)
void flash_mma(const float* __restrict__ qkv, float* __restrict__ out) {
    extern __shared__ uint32_t fsm[];
    uint32_t* QH = fsm;
    uint32_t* QL = QH + FARR;
    uint32_t* KH = QL + FARR;
    uint32_t* KL = KH + FARR;
    uint32_t* VH = KL + FARR;
    uint32_t* VL = VH + FARR;

    const int tid = threadIdx.x;
    const int wid = tid >> 5, lane = tid & 31;
    const int g = lane >> 2, t = lane & 3;

    const int qb = blockIdx.x;
    const int bh = blockIdx.y;
    const int b = bh >> 5;
    const int h = bh & 31;

    const float slope = exp2f(-0.25f * (float)(h + 1));
    const float scale = 8.0f / (float)D_;

    const size_t base = (size_t)b * T_ * THREE_E;
    const float* Qg = qkv + base + (size_t)h * D_;
    const float* Kg = qkv + base + E_ + (size_t)h * D_;
    const float* Vg = qkv + base + 2 * E_ + (size_t)h * D_;

    const int q0 = qb * 64;

    for (int i = tid; i < 64 * 32; i += 128) {
        int r = i >> 5, dp = i & 31;
        const float* p = Qg + (size_t)(q0 + r) * THREE_E + dp * 2;
        uint32_t hi, lo;
        split2(p[0] * scale, p[1] * scale, hi, lo);
        QH[r * FST + dp] = hi;
        QL[r * FST + dp] = lo;
    }

    float o[8][4];
#pragma unroll
    for (int nf = 0; nf < 8; nf++)
#pragma unroll
        for (int r = 0; r < 4; r++) o[nf][r] = 0.0f;
    float m0 = -1e30f, m1 = -1e30f, l0 = 0.0f, l1 = 0.0f;

    const int rW = wid * 16;
    const int qg0 = q0 + rW + g;
    const int qg1 = qg0 + 8;

    for (int kb = 0; kb <= qb; kb++) {
        __syncthreads();
        for (int i = tid; i < 64 * 32; i += 128) {
            int r = i >> 5, dp = i & 31;
            const float* p = Kg + (size_t)(kb * 64 + r) * THREE_E + dp * 2;
            uint32_t hi, lo;
            split2(p[0], p[1], hi, lo);
            KH[r * FST + dp] = hi;
            KL[r * FST + dp] = lo;
        }
        for (int i = tid; i < 64 * 32; i += 128) {
            int d = i & 63, kp = i >> 6;
            const float* p = Vg + (size_t)(kb * 64 + kp * 2) * THREE_E + d;
            uint32_t hi, lo;
            split2(p[0], p[THREE_E], hi, lo);
            VH[d * FST + kp] = hi;
            VL[d * FST + kp] = lo;
        }
        __syncthreads();

        float c[8][4];
#pragma unroll
        for (int nf = 0; nf < 8; nf++)
#pragma unroll
            for (int r = 0; r < 4; r++) c[nf][r] = 0.0f;

#pragma unroll
        for (int kt = 0; kt < 4; kt++) {
            uint32_t ah[4], al[4];
            ah[0] = QH[(rW + g) * FST + kt * 8 + t];
            ah[1] = QH[(rW + g + 8) * FST + kt * 8 + t];
            ah[2] = QH[(rW + g) * FST + kt * 8 + t + 4];
            ah[3] = QH[(rW + g + 8) * FST + kt * 8 + t + 4];
            al[0] = QL[(rW + g) * FST + kt * 8 + t];
            al[1] = QL[(rW + g + 8) * FST + kt * 8 + t];
            al[2] = QL[(rW + g) * FST + kt * 8 + t + 4];
            al[3] = QL[(rW + g + 8) * FST + kt * 8 + t + 4];
#pragma unroll
            for (int nf = 0; nf < 8; nf++) {
                const int rB = (8 * nf + g) * FST + kt * 8 + t;
                uint32_t bh0 = KH[rB], bh1 = KH[rB + 4];
                uint32_t bl0 = KL[rB], bl1 = KL[rB + 4];
                mma_bf16(c[nf], ah, bh0, bh1);
                mma_bf16(c[nf], al, bh0, bh1);
                mma_bf16(c[nf], ah, bl0, bl1);
            }
        }

#pragma unroll
        for (int nf = 0; nf < 8; nf++) {
            const int col0 = kb * 64 + 8 * nf + 2 * t;
            const int col1 = col0 + 1;
            c[nf][0] = (col0 > qg0) ? -1e30f : c[nf][0] + slope * (float)(col0 - qg0);
            c[nf][1] = (col1 > qg0) ? -1e30f : c[nf][1] + slope * (float)(col1 - qg0);
            c[nf][2] = (col0 > qg1) ? -1e30f : c[nf][2] + slope * (float)(col0 - qg1);
            c[nf][3] = (col1 > qg1) ? -1e30f : c[nf][3] + slope * (float)(col1 - qg1);
        }

        float mx0 = -1e30f, mx1 = -1e30f;
#pragma unroll
        for (int nf = 0; nf < 8; nf++) {
            mx0 = fmaxf(mx0, fmaxf(c[nf][0], c[nf][1]));
            mx1 = fmaxf(mx1, fmaxf(c[nf][2], c[nf][3]));
        }
        mx0 = fmaxf(mx0, __shfl_xor_sync(0xffffffffu, mx0, 1));
        mx0 = fmaxf(mx0, __shfl_xor_sync(0xffffffffu, mx0, 2));
        mx1 = fmaxf(mx1, __shfl_xor_sync(0xffffffffu, mx1, 1));
        mx1 = fmaxf(mx1, __shfl_xor_sync(0xffffffffu, mx1, 2));

        const float mn0 = fmaxf(m0, mx0), mn1 = fmaxf(m1, mx1);
        const float alpha0 = __expf(m0 - mn0), alpha1 = __expf(m1 - mn1);
        m0 = mn0; m1 = mn1;

        float s0 = 0.0f, s1 = 0.0f;
#pragma unroll
        for (int nf = 0; nf < 8; nf++) {
            c[nf][0] = __expf(c[nf][0] - m0);
            c[nf][1] = __expf(c[nf][1] - m0);
            c[nf][2] = __expf(c[nf][2] - m1);
            c[nf][3] = __expf(c[nf][3] - m1);
            s0 += c[nf][0] + c[nf][1];
            s1 += c[nf][2] + c[nf][3];
        }
        s0 += __shfl_xor_sync(0xffffffffu, s0, 1);
        s0 += __shfl_xor_sync(0xffffffffu, s0, 2);
        s1 += __shfl_xor_sync(0xffffffffu, s1, 1);
        s1 += __shfl_xor_sync(0xffffffffu, s1, 2);
        l0 = l0 * alpha0 + s0;
        l1 = l1 * alpha1 + s1;

        uint32_t pah[4][4], pal[4][4];
#pragma unroll
        for (int kt = 0; kt < 4; kt++) {
            split2(c[2 * kt][0],     c[2 * kt][1],     pah[kt][0], pal[kt][0]);
            split2(c[2 * kt][2],     c[2 * kt][3],     pah[kt][1], pal[kt][1]);
            split2(c[2 * kt + 1][0], c[2 * kt + 1][1], pah[kt][2], pal[kt][2]);
            split2(c[2 * kt + 1][2], c[2 * kt + 1][3], pah[kt][3], pal[kt][3]);
        }

#pragma unroll
        for (int nf = 0; nf < 8; nf++) {
            o[nf][0] *= alpha0; o[nf][1] *= alpha0;
            o[nf][2] *= alpha1; o[nf][3] *= alpha1;
        }

#pragma unroll
        for (int kt = 0; kt < 4; kt++) {
#pragma unroll
            for (int nf = 0; nf < 8; nf++) {
                const int rB = (8 * nf + g) * FST + kt * 8 + t;
                uint32_t bh0 = VH[rB], bh1 = VH[rB + 4];
                uint32_t bl0 = VL[rB], bl1 = VL[rB + 4];
                mma_bf16(o[nf], pah[kt], bh0, bh1);
                mma_bf16(o[nf], pal[kt], bh0, bh1);
                mma_bf16(o[nf], pah[kt], bl0, bl1);
            }
        }
    }

    // epilogue: normalize, round to tf32 bits (out-proj GEMM needs no cvt)
    const float inv0 = 1.0f / l0, inv1 = 1.0f / l1;
    float* o0 = out + ((size_t)b * T_ + qg0) * E_ + h * D_;
    float* o1 = out + ((size_t)b * T_ + qg1) * E_ + h * D_;
#pragma unroll
    for (int nf = 0; nf < 8; nf++) {
        const int col = 8 * nf + 2 * t;
        float2 v0 = { __uint_as_float(f2tf32(o[nf][0] * inv0)),
                      __uint_as_float(f2tf32(o[nf][1] * inv0)) };
        float2 v1 = { __uint_as_float(f2tf32(o[nf][2] * inv1)),
                      __uint_as_float(f2tf32(o[nf][3] * inv1)) };
        *(float2*)(o0 + col) = v0;
        *(float2*)(o1 + col) = v1;
    }
}

// ---------------------------------------------------------------------------
extern "C" void kernel_launch(void* const* d_in, const int* in_sizes, int n_in,
                              void* d_out, int out_size) {
    const float* x    = (const float*)d_in[0];
    const float* Wqkv = (const float*)d_in[1];
    const float* bqkv = (const float*)d_in[2];
    const float* Wout = (const float*)d_in[3];
    const float* bout = (const float*)d_in[4];
    float* out = (float*)d_out;

    float *qkv, *att, *rx, *rwq, *rwo;
    cudaGetSymbolAddress((void**)&qkv, g_qkv);
    cudaGetSymbolAddress((void**)&att, g_att);
    cudaGetSymbolAddress((void**)&rx,  g_rx);
    cudaGetSymbolAddress((void**)&rwq, g_rwq);
    cudaGetSymbolAddress((void**)&rwo, g_rwo);

    cudaFuncSetAttribute(flash_mma, cudaFuncAttributeMaxDynamicSharedMemorySize, FLASH_SMEM);

    // 0) pre-round inputs/weights to tf32 bit patterns
    {
        int n4;
        n4 = (B_ * T_ * E_) / 4;
        round_tf32<<<(n4 + 255) / 256, 256>>>((const float4*)x, (float4*)rx, n4);
        n4 = (E_ * THREE_E) / 4;
        round_tf32<<<(n4 + 255) / 256, 256>>>((const float4*)Wqkv, (float4*)rwq, n4);
        n4 = (E_ * E_) / 4;
        round_tf32<<<(n4 + 255) / 256, 256>>>((const float4*)Wout, (float4*)rwo, n4);
    }

    // 1) QKV projection (tf32 tensor cores, pre-rounded operands)
    mma_gemm<<<dim3(THREE_E / BN, (B_ * T_) / BM), NTHR>>>(
        B_ * T_, THREE_E, E_, rx, rwq, bqkv, qkv);

    // 2) Flash attention (bf16 3-term tensor cores; epilogue rounds att)
    flash_mma<<<dim3(T_ / 64, B_ * H_), 128, FLASH_SMEM>>>(qkv, att);

    // 3) Output projection (tf32 tensor cores, pre-rounded operands)
    mma_gemm<<<dim3(E_ / BN, (B_ * T_) / BM), NTHR>>>(
        B_ * T_, E_, E_, att, rwo, bout, out);
}

// round 7
// speedup vs baseline: 3.0628x; 1.0195x over previous
#include <cuda_runtime.h>
#include <cuda_bf16.h>
#include <cstdint>

#define B_ 2
#define T_ 2048
#define E_ 2048
#define H_ 32
#define D_ 64
#define THREE_E (3 * E_)

// Scratch (no allocs allowed anywhere).
__device__ float g_qkv[(size_t)B_ * T_ * THREE_E];   // 96 MB
__device__ float g_att[(size_t)B_ * T_ * E_];        // 32 MB (tf32-rounded by flash epilogue)
__device__ float g_rx[(size_t)B_ * T_ * E_];         // 32 MB (x rounded to tf32)
__device__ float g_rwq[(size_t)E_ * THREE_E];        // 48 MB (Wqkv rounded)
__device__ float g_rwo[(size_t)E_ * E_];             // 16 MB (Wout rounded)

// ---------------------------------------------------------------------------
// helpers
// ---------------------------------------------------------------------------
__device__ __forceinline__ uint32_t smem_u32(const void* p) {
    uint32_t a;
    asm("{ .reg .u64 t; cvta.to.shared.u64 t, %1; cvt.u32.u64 %0, t; }" : "=r"(a) : "l"(p));
    return a;
}
#define CP_ASYNC16(dst, src) \
    asm volatile("cp.async.cg.shared.global [%0], [%1], 16;" :: "r"(dst), "l"(src))
#define CP_COMMIT() asm volatile("cp.async.commit_group;" ::: "memory")
#define CP_WAITG(n) asm volatile("cp.async.wait_group %0;" :: "n"(n) : "memory")

__device__ __forceinline__ uint32_t f2tf32(float x) {
    uint32_t r;
    asm("cvt.rna.tf32.f32 %0, %1;" : "=r"(r) : "f"(x));
    return r;
}

// m16n8k8 tf32 MMA (operands pre-rounded to tf32 bit patterns)
__device__ __forceinline__ void mma_tf32(float* c, const uint32_t* a, const uint32_t* b) {
    asm volatile(
        "mma.sync.aligned.m16n8k8.row.col.f32.tf32.tf32.f32 "
        "{%0,%1,%2,%3}, {%4,%5,%6,%7}, {%8,%9}, {%0,%1,%2,%3};"
        : "+f"(c[0]), "+f"(c[1]), "+f"(c[2]), "+f"(c[3])
        : "r"(a[0]), "r"(a[1]), "r"(a[2]), "r"(a[3]), "r"(b[0]), "r"(b[1]));
}

// m16n8k16 bf16 MMA
__device__ __forceinline__ void mma_bf16(float* c, const uint32_t* a, uint32_t b0, uint32_t b1) {
    asm volatile(
        "mma.sync.aligned.m16n8k16.row.col.f32.bf16.bf16.f32 "
        "{%0,%1,%2,%3}, {%4,%5,%6,%7}, {%8,%9}, {%0,%1,%2,%3};"
        : "+f"(c[0]), "+f"(c[1]), "+f"(c[2]), "+f"(c[3])
        : "r"(a[0]), "r"(a[1]), "r"(a[2]), "r"(a[3]), "r"(b0), "r"(b1));
}

// split (x,y) into hi/lo bf16x2 words
__device__ __forceinline__ void split2(float x, float y, uint32_t& hi, uint32_t& lo) {
    __nv_bfloat16 hx = __float2bfloat16(x);
    __nv_bfloat16 hy = __float2bfloat16(y);
    __nv_bfloat16 lx = __float2bfloat16(x - __bfloat162float(hx));
    __nv_bfloat16 ly = __float2bfloat16(y - __bfloat162float(hy));
    hi = ((uint32_t)__bfloat16_as_ushort(hy) << 16) | __bfloat16_as_ushort(hx);
    lo = ((uint32_t)__bfloat16_as_ushort(ly) << 16) | __bfloat16_as_ushort(lx);
}

// ---------------------------------------------------------------------------
// Pre-round fp32 -> tf32 bit patterns (elementwise, float4)
// ---------------------------------------------------------------------------
__global__ void round_tf32(const float4* __restrict__ in, float4* __restrict__ out, int n4) {
    int i = blockIdx.x * blockDim.x + threadIdx.x;
    if (i < n4) {
        float4 v = in[i];
        float4 r;
        r.x = __uint_as_float(f2tf32(v.x));
        r.y = __uint_as_float(f2tf32(v.y));
        r.z = __uint_as_float(f2tf32(v.z));
        r.w = __uint_as_float(f2tf32(v.w));
        out[i] = r;
    }
}

// ---------------------------------------------------------------------------
// tf32 tensor-core GEMM: C = A @ W + bias. A and W PRE-ROUNDED to tf32 bits.
// CTA 128x128, BK=16, 256 threads (8 warps: 2x4), warp tile 64x32.
// 4-stage cp.async pipeline, ONE __syncthreads per tile.
// ---------------------------------------------------------------------------
#define BM 128
#define BN 128
#define BK 16
#define APAD 20
#define BPAD 136
#define NTHR 256
#define STAGES 4

struct SmemTile {
    float As[BM][APAD];
    float Bs[BK][BPAD];
};
#define GEMM_SMEM (STAGES * (int)sizeof(SmemTile))

__device__ __forceinline__ void gemm_load_tile(SmemTile* st,
                                               const float* __restrict__ Ab,
                                               const float* __restrict__ Wb,
                                               int K, int N, int k0, int tid) {
#pragma unroll
    for (int it = 0; it < 2; it++) {
        int idx = tid + NTHR * it;
        int m = idx >> 2, kc = idx & 3;
        CP_ASYNC16(smem_u32(&st->As[m][kc * 4]), Ab + (size_t)m * K + k0 + kc * 4);
    }
#pragma unroll
    for (int it = 0; it < 2; it++) {
        int idx = tid + NTHR * it;
        int k = idx >> 5, c = idx & 31;
        CP_ASYNC16(smem_u32(&st->Bs[k][c * 4]), Wb + (size_t)(k0 + k) * N + c * 4);
    }
    CP_COMMIT();
}

__global__ __launch_bounds__(NTHR)
void mma_gemm(int M, int N, int K,
              const float* __restrict__ A,
              const float* __restrict__ W,
              const float* __restrict__ bias,
              float* __restrict__ C) {
    extern __shared__ SmemTile sm[];   // [STAGES]

    const int tid = threadIdx.x;
    const int wid = tid >> 5, lane = tid & 31;
    const int wm = wid >> 2, wn = wid & 3;
    const int g = lane >> 2, t = lane & 3;

    const int m0 = blockIdx.y * BM;
    const int n0 = blockIdx.x * BN;

    const float* Ab = A + (size_t)m0 * K;
    const float* Wb = W + n0;

    float acc[4][4][4];
#pragma unroll
    for (int i = 0; i < 4; i++)
#pragma unroll
        for (int j = 0; j < 4; j++)
#pragma unroll
            for (int r = 0; r < 4; r++) acc[i][j][r] = 0.0f;

    const int NT = K / BK;

    // prologue: stages 0..STAGES-2
#pragma unroll
    for (int s = 0; s < STAGES - 1; s++)
        gemm_load_tile(&sm[s], Ab, Wb, K, N, s * BK, tid);

    for (int kt = 0; kt < NT; kt++) {
        // wait for tile kt: allowed pending groups = min(STAGES-2, NT-1-kt)
        const int rem = NT - 1 - kt;
        if (rem >= STAGES - 2)      CP_WAITG(STAGES - 2);
        else if (rem == 1)          CP_WAITG(1);
        else                        CP_WAITG(0);
        __syncthreads();   // tile kt visible to all; buffer (kt+STAGES-1)%S free

        // issue load for tile kt+STAGES-1 (overlaps with compute below)
        if (kt + STAGES - 1 < NT)
            gemm_load_tile(&sm[(kt + STAGES - 1) % STAGES], Ab, Wb, K, N,
                           (kt + STAGES - 1) * BK, tid);

        const SmemTile& S = sm[kt % STAGES];
#pragma unroll
        for (int ks = 0; ks < 2; ks++) {
            const int kk = ks * 8;
            uint32_t af[4][4], bf[4][2];
#pragma unroll
            for (int mf = 0; mf < 4; mf++) {
                const int rA = wm * 64 + mf * 16;
                af[mf][0] = __float_as_uint(S.As[rA + g][kk + t]);
                af[mf][1] = __float_as_uint(S.As[rA + g + 8][kk + t]);
                af[mf][2] = __float_as_uint(S.As[rA + g][kk + t + 4]);
                af[mf][3] = __float_as_uint(S.As[rA + g + 8][kk + t + 4]);
            }
#pragma unroll
            for (int nf = 0; nf < 4; nf++) {
                const int cB = wn * 32 + nf * 8 + g;
                bf[nf][0] = __float_as_uint(S.Bs[kk + t][cB]);
                bf[nf][1] = __float_as_uint(S.Bs[kk + t + 4][cB]);
            }
#pragma unroll
            for (int mf = 0; mf < 4; mf++)
#pragma unroll
                for (int nf = 0; nf < 4; nf++)
                    mma_tf32(acc[mf][nf], af[mf], bf[nf]);
        }
    }

#pragma unroll
    for (int mf = 0; mf < 4; mf++) {
        const int row = m0 + wm * 64 + mf * 16 + g;
#pragma unroll
        for (int nf = 0; nf < 4; nf++) {
            const int col = n0 + wn * 32 + nf * 8 + 2 * t;
            const float b0 = bias[col], b1 = bias[col + 1];
            float2 v0 = { acc[mf][nf][0] + b0, acc[mf][nf][1] + b1 };
            float2 v1 = { acc[mf][nf][2] + b0, acc[mf][nf][3] + b1 };
            *(float2*)(C + (size_t)row * N + col) = v0;
            *(float2*)(C + (size_t)(row + 8) * N + col) = v1;
        }
    }
}

// ---------------------------------------------------------------------------
// Tensor-core flash attention: bf16 3-term split, ALiBi + causal.
// Epilogue stores tf32-ROUNDED values (feeds the pre-rounded out-proj GEMM).
// ---------------------------------------------------------------------------
#define FST 36
#define FARR (64 * FST)
#define FLASH_SMEM (6 * FARR * 4)

__global__ __launch_bounds__(128)
void flash_mma(const float* __restrict__ qkv, float* __restrict__ out) {
    extern __shared__ uint32_t fsm[];
    uint32_t* QH = fsm;
    uint32_t* QL = QH + FARR;
    uint32_t* KH = QL + FARR;
    uint32_t* KL = KH + FARR;
    uint32_t* VH = KL + FARR;
    uint32_t* VL = VH + FARR;

    const int tid = threadIdx.x;
    const int wid = tid >> 5, lane = tid & 31;
    const int g = lane >> 2, t = lane & 3;

    const int qb = blockIdx.x;
    const int bh = blockIdx.y;
    const int b = bh >> 5;
    const int h = bh & 31;

    const float slope = exp2f(-0.25f * (float)(h + 1));
    const float scale = 8.0f / (float)D_;

    const size_t base = (size_t)b * T_ * THREE_E;
    const float* Qg = qkv + base + (size_t)h * D_;
    const float* Kg = qkv + base + E_ + (size_t)h * D_;
    const float* Vg = qkv + base + 2 * E_ + (size_t)h * D_;

    const int q0 = qb * 64;

    for (int i = tid; i < 64 * 32; i += 128) {
        int r = i >> 5, dp = i & 31;
        const float* p = Qg + (size_t)(q0 + r) * THREE_E + dp * 2;
        uint32_t hi, lo;
        split2(p[0] * scale, p[1] * scale, hi, lo);
        QH[r * FST + dp] = hi;
        QL[r * FST + dp] = lo;
    }

    float o[8][4];
#pragma unroll
    for (int nf = 0; nf < 8; nf++)
#pragma unroll
        for (int r = 0; r < 4; r++) o[nf][r] = 0.0f;
    float m0 = -1e30f, m1 = -1e30f, l0 = 0.0f, l1 = 0.0f;

    const int rW = wid * 16;
    const int qg0 = q0 + rW + g;
    const int qg1 = qg0 + 8;

    for (int kb = 0; kb <= qb; kb++) {
        __syncthreads();
        for (int i = tid; i < 64 * 32; i += 128) {
            int r = i >> 5, dp = i & 31;
            const float* p = Kg + (size_t)(kb * 64 + r) * THREE_E + dp * 2;
            uint32_t hi, lo;
            split2(p[0], p[1], hi, lo);
            KH[r * FST + dp] = hi;
            KL[r * FST + dp] = lo;
        }
        for (int i = tid; i < 64 * 32; i += 128) {
            int d = i & 63, kp = i >> 6;
            const float* p = Vg + (size_t)(kb * 64 + kp * 2) * THREE_E + d;
            uint32_t hi, lo;
            split2(p[0], p[THREE_E], hi, lo);
            VH[d * FST + kp] = hi;
            VL[d * FST + kp] = lo;
        }
        __syncthreads();

        float c[8][4];
#pragma unroll
        for (int nf = 0; nf < 8; nf++)
#pragma unroll
            for (int r = 0; r < 4; r++) c[nf][r] = 0.0f;

#pragma unroll
        for (int kt = 0; kt < 4; kt++) {
            uint32_t ah[4], al[4];
            ah[0] = QH[(rW + g) * FST + kt * 8 + t];
            ah[1] = QH[(rW + g + 8) * FST + kt * 8 + t];
            ah[2] = QH[(rW + g) * FST + kt * 8 + t + 4];
            ah[3] = QH[(rW + g + 8) * FST + kt * 8 + t + 4];
            al[0] = QL[(rW + g) * FST + kt * 8 + t];
            al[1] = QL[(rW + g + 8) * FST + kt * 8 + t];
            al[2] = QL[(rW + g) * FST + kt * 8 + t + 4];
            al[3] = QL[(rW + g + 8) * FST + kt * 8 + t + 4];
#pragma unroll
            for (int nf = 0; nf < 8; nf++) {
                const int rB = (8 * nf + g) * FST + kt * 8 + t;
                uint32_t bh0 = KH[rB], bh1 = KH[rB + 4];
                uint32_t bl0 = KL[rB], bl1 = KL[rB + 4];
                mma_bf16(c[nf], ah, bh0, bh1);
                mma_bf16(c[nf], al, bh0, bh1);
                mma_bf16(c[nf], ah, bl0, bl1);
            }
        }

#pragma unroll
        for (int nf = 0; nf < 8; nf++) {
            const int col0 = kb * 64 + 8 * nf + 2 * t;
            const int col1 = col0 + 1;
            c[nf][0] = (col0 > qg0) ? -1e30f : c[nf][0] + slope * (float)(col0 - qg0);
            c[nf][1] = (col1 > qg0) ? -1e30f : c[nf][1] + slope * (float)(col1 - qg0);
            c[nf][2] = (col0 > qg1) ? -1e30f : c[nf][2] + slope * (float)(col0 - qg1);
            c[nf][3] = (col1 > qg1) ? -1e30f : c[nf][3] + slope * (float)(col1 - qg1);
        }

        float mx0 = -1e30f, mx1 = -1e30f;
#pragma unroll
        for (int nf = 0; nf < 8; nf++) {
            mx0 = fmaxf(mx0, fmaxf(c[nf][0], c[nf][1]));
            mx1 = fmaxf(mx1, fmaxf(c[nf][2], c[nf][3]));
        }
        mx0 = fmaxf(mx0, __shfl_xor_sync(0xffffffffu, mx0, 1));
        mx0 = fmaxf(mx0, __shfl_xor_sync(0xffffffffu, mx0, 2));
        mx1 = fmaxf(mx1, __shfl_xor_sync(0xffffffffu, mx1, 1));
        mx1 = fmaxf(mx1, __shfl_xor_sync(0xffffffffu, mx1, 2));

        const float mn0 = fmaxf(m0, mx0), mn1 = fmaxf(m1, mx1);
        const float alpha0 = __expf(m0 - mn0), alpha1 = __expf(m1 - mn1);
        m0 = mn0; m1 = mn1;

        float s0 = 0.0f, s1 = 0.0f;
#pragma unroll
        for (int nf = 0; nf < 8; nf++) {
            c[nf][0] = __expf(c[nf][0] - m0);
            c[nf][1] = __expf(c[nf][1] - m0);
            c[nf][2] = __expf(c[nf][2] - m1);
            c[nf][3] = __expf(c[nf][3] - m1);
            s0 += c[nf][0] + c[nf][1];
            s1 += c[nf][2] + c[nf][3];
        }
        s0 += __shfl_xor_sync(0xffffffffu, s0, 1);
        s0 += __shfl_xor_sync(0xffffffffu, s0, 2);
        s1 += __shfl_xor_sync(0xffffffffu, s1, 1);
        s1 += __shfl_xor_sync(0xffffffffu, s1, 2);
        l0 = l0 * alpha0 + s0;
        l1 = l1 * alpha1 + s1;

        uint32_t pah[4][4], pal[4][4];
#pragma unroll
        for (int kt = 0; kt < 4; kt++) {
            split2(c[2 * kt][0],     c[2 * kt][1],     pah[kt][0], pal[kt][0]);
            split2(c[2 * kt][2],     c[2 * kt][3],     pah[kt][1], pal[kt][1]);
            split2(c[2 * kt + 1][0], c[2 * kt + 1][1], pah[kt][2], pal[kt][2]);
            split2(c[2 * kt + 1][2], c[2 * kt + 1][3], pah[kt][3], pal[kt][3]);
        }

#pragma unroll
        for (int nf = 0; nf < 8; nf++) {
            o[nf][0] *= alpha0; o[nf][1] *= alpha0;
            o[nf][2] *= alpha1; o[nf][3] *= alpha1;
        }

#pragma unroll
        for (int kt = 0; kt < 4; kt++) {
#pragma unroll
            for (int nf = 0; nf < 8; nf++) {
                const int rB = (8 * nf + g) * FST + kt * 8 + t;
                uint32_t bh0 = VH[rB], bh1 = VH[rB + 4];
                uint32_t bl0 = VL[rB], bl1 = VL[rB + 4];
                mma_bf16(o[nf], pah[kt], bh0, bh1);
                mma_bf16(o[nf], pal[kt], bh0, bh1);
                mma_bf16(o[nf], pah[kt], bl0, bl1);
            }
        }
    }

    // epilogue: normalize, round to tf32 bits (out-proj GEMM needs no cvt)
    const float inv0 = 1.0f / l0, inv1 = 1.0f / l1;
    float* o0 = out + ((size_t)b * T_ + qg0) * E_ + h * D_;
    float* o1 = out + ((size_t)b * T_ + qg1) * E_ + h * D_;
#pragma unroll
    for (int nf = 0; nf < 8; nf++) {
        const int col = 8 * nf + 2 * t;
        float2 v0 = { __uint_as_float(f2tf32(o[nf][0] * inv0)),
                      __uint_as_float(f2tf32(o[nf][1] * inv0)) };
        float2 v1 = { __uint_as_float(f2tf32(o[nf][2] * inv1)),
                      __uint_as_float(f2tf32(o[nf][3] * inv1)) };
        *(float2*)(o0 + col) = v0;
        *(float2*)(o1 + col) = v1;
    }
}

// ---------------------------------------------------------------------------
extern "C" void kernel_launch(void* const* d_in, const int* in_sizes, int n_in,
                              void* d_out, int out_size) {
    const float* x    = (const float*)d_in[0];
    const float* Wqkv = (const float*)d_in[1];
    const float* bqkv = (const float*)d_in[2];
    const float* Wout = (const float*)d_in[3];
    const float* bout = (const float*)d_in[4];
    float* out = (float*)d_out;

    float *qkv, *att, *rx, *rwq, *rwo;
    cudaGetSymbolAddress((void**)&qkv, g_qkv);
    cudaGetSymbolAddress((void**)&att, g_att);
    cudaGetSymbolAddress((void**)&rx,  g_rx);
    cudaGetSymbolAddress((void**)&rwq, g_rwq);
    cudaGetSymbolAddress((void**)&rwo, g_rwo);

    cudaFuncSetAttribute(flash_mma, cudaFuncAttributeMaxDynamicSharedMemorySize, FLASH_SMEM);
    cudaFuncSetAttribute(mma_gemm, cudaFuncAttributeMaxDynamicSharedMemorySize, GEMM_SMEM);

    // 0) pre-round inputs/weights to tf32 bit patterns
    {
        int n4;
        n4 = (B_ * T_ * E_) / 4;
        round_tf32<<<(n4 + 255) / 256, 256>>>((const float4*)x, (float4*)rx, n4);
        n4 = (E_ * THREE_E) / 4;
        round_tf32<<<(n4 + 255) / 256, 256>>>((const float4*)Wqkv, (float4*)rwq, n4);
        n4 = (E_ * E_) / 4;
        round_tf32<<<(n4 + 255) / 256, 256>>>((const float4*)Wout, (float4*)rwo, n4);
    }

    // 1) QKV projection (tf32 tensor cores, pre-rounded operands)
    mma_gemm<<<dim3(THREE_E / BN, (B_ * T_) / BM), NTHR, GEMM_SMEM>>>(
        B_ * T_, THREE_E, E_, rx, rwq, bqkv, qkv);

    // 2) Flash attention (bf16 3-term tensor cores; epilogue rounds att)
    flash_mma<<<dim3(T_ / 64, B_ * H_), 128, FLASH_SMEM>>>(qkv, att);

    // 3) Output projection (tf32 tensor cores, pre-rounded operands)
    mma_gemm<<<dim3(E_ / BN, (B_ * T_) / BM), NTHR, GEMM_SMEM>>>(
        B_ * T_, E_, E_, att, rwo, bout, out);
}

// round 8
// speedup vs baseline: 3.2142x; 1.0494x over previous
#include <cuda_runtime.h>
#include <cuda_bf16.h>
#include <cstdint>

#define B_ 2
#define T_ 2048
#define E_ 2048
#define H_ 32
#define D_ 64
#define THREE_E (3 * E_)

// Scratch (no allocs allowed anywhere).
__device__ float g_qkv[(size_t)B_ * T_ * THREE_E];   // 96 MB
__device__ float g_att[(size_t)B_ * T_ * E_];        // 32 MB (tf32-rounded by flash epilogue)
__device__ float g_rx[(size_t)B_ * T_ * E_];         // 32 MB (x rounded to tf32)
__device__ float g_rwq[(size_t)E_ * THREE_E];        // 48 MB (Wqkv rounded)
__device__ float g_rwo[(size_t)E_ * E_];             // 16 MB (Wout rounded)

// ---------------------------------------------------------------------------
// helpers
// ---------------------------------------------------------------------------
__device__ __forceinline__ uint32_t smem_u32(const void* p) {
    uint32_t a;
    asm("{ .reg .u64 t; cvta.to.shared.u64 t, %1; cvt.u32.u64 %0, t; }" : "=r"(a) : "l"(p));
    return a;
}
#define CP_ASYNC16(dst, src) \
    asm volatile("cp.async.cg.shared.global [%0], [%1], 16;" :: "r"(dst), "l"(src))
#define CP_COMMIT() asm volatile("cp.async.commit_group;" ::: "memory")
#define CP_WAITG(n) asm volatile("cp.async.wait_group %0;" :: "n"(n) : "memory")

// ldmatrix x4: four 8x8 b16 matrices (== four 8x4 tf32 quadrants)
#define LDSM_X4(r, a)                                                            \
    asm volatile("ldmatrix.sync.aligned.m8n8.x4.shared.b16 {%0,%1,%2,%3}, [%4];" \
        : "=r"((r)[0]), "=r"((r)[1]), "=r"((r)[2]), "=r"((r)[3]) : "r"(a))

__device__ __forceinline__ uint32_t f2tf32(float x) {
    uint32_t r;
    asm("cvt.rna.tf32.f32 %0, %1;" : "=r"(r) : "f"(x));
    return r;
}

// m16n8k8 tf32 MMA (operands pre-rounded to tf32 bit patterns)
__device__ __forceinline__ void mma_tf32(float* c, const uint32_t* a, const uint32_t* b) {
    asm volatile(
        "mma.sync.aligned.m16n8k8.row.col.f32.tf32.tf32.f32 "
        "{%0,%1,%2,%3}, {%4,%5,%6,%7}, {%8,%9}, {%0,%1,%2,%3};"
        : "+f"(c[0]), "+f"(c[1]), "+f"(c[2]), "+f"(c[3])
        : "r"(a[0]), "r"(a[1]), "r"(a[2]), "r"(a[3]), "r"(b[0]), "r"(b[1]));
}

// m16n8k16 bf16 MMA
__device__ __forceinline__ void mma_bf16(float* c, const uint32_t* a, uint32_t b0, uint32_t b1) {
    asm volatile(
        "mma.sync.aligned.m16n8k16.row.col.f32.bf16.bf16.f32 "
        "{%0,%1,%2,%3}, {%4,%5,%6,%7}, {%8,%9}, {%0,%1,%2,%3};"
        : "+f"(c[0]), "+f"(c[1]), "+f"(c[2]), "+f"(c[3])
        : "r"(a[0]), "r"(a[1]), "r"(a[2]), "r"(a[3]), "r"(b0), "r"(b1));
}

// split (x,y) into hi/lo bf16x2 words
__device__ __forceinline__ void split2(float x, float y, uint32_t& hi, uint32_t& lo) {
    __nv_bfloat16 hx = __float2bfloat16(x);
    __nv_bfloat16 hy = __float2bfloat16(y);
    __nv_bfloat16 lx = __float2bfloat16(x - __bfloat162float(hx));
    __nv_bfloat16 ly = __float2bfloat16(y - __bfloat162float(hy));
    hi = ((uint32_t)__bfloat16_as_ushort(hy) << 16) | __bfloat16_as_ushort(hx);
    lo = ((uint32_t)__bfloat16_as_ushort(ly) << 16) | __bfloat16_as_ushort(lx);
}

// ---------------------------------------------------------------------------
// Pre-round fp32 -> tf32 bit patterns (elementwise, float4)
// ---------------------------------------------------------------------------
__global__ void round_tf32(const float4* __restrict__ in, float4* __restrict__ out, int n4) {
    int i = blockIdx.x * blockDim.x + threadIdx.x;
    if (i < n4) {
        float4 v = in[i];
        float4 r;
        r.x = __uint_as_float(f2tf32(v.x));
        r.y = __uint_as_float(f2tf32(v.y));
        r.z = __uint_as_float(f2tf32(v.z));
        r.w = __uint_as_float(f2tf32(v.w));
        out[i] = r;
    }
}

// ---------------------------------------------------------------------------
// tf32 tensor-core GEMM: C = A @ W + bias. A and W PRE-ROUNDED to tf32 bits.
// CTA 128x128, BK=16, 256 threads (8 warps: 2x4), warp tile 64x32.
// 4-stage cp.async pipeline, one __syncthreads per tile.
// A-fragments via ldmatrix.x4 (4/k-step); B via scalar LDS (8/k-step).
// ---------------------------------------------------------------------------
#define BM 128
#define BN 128
#define BK 16
#define APAD 20
#define BPAD 136
#define NTHR 256
#define STAGES 4

struct SmemTile {
    float As[BM][APAD];
    float Bs[BK][BPAD];
};
#define GEMM_SMEM (STAGES * (int)sizeof(SmemTile))

__device__ __forceinline__ void gemm_load_tile(SmemTile* st,
                                               const float* __restrict__ Ab,
                                               const float* __restrict__ Wb,
                                               int K, int N, int k0, int tid) {
#pragma unroll
    for (int it = 0; it < 2; it++) {
        int idx = tid + NTHR * it;
        int m = idx >> 2, kc = idx & 3;
        CP_ASYNC16(smem_u32(&st->As[m][kc * 4]), Ab + (size_t)m * K + k0 + kc * 4);
    }
#pragma unroll
    for (int it = 0; it < 2; it++) {
        int idx = tid + NTHR * it;
        int k = idx >> 5, c = idx & 31;
        CP_ASYNC16(smem_u32(&st->Bs[k][c * 4]), Wb + (size_t)(k0 + k) * N + c * 4);
    }
    CP_COMMIT();
}

__global__ __launch_bounds__(NTHR, 2)
void mma_gemm(int M, int N, int K,
              const float* __restrict__ A,
              const float* __restrict__ W,
              const float* __restrict__ bias,
              float* __restrict__ C) {
    extern __shared__ SmemTile sm[];   // [STAGES]

    const int tid = threadIdx.x;
    const int wid = tid >> 5, lane = tid & 31;
    const int wm = wid >> 2, wn = wid & 3;
    const int g = lane >> 2, t = lane & 3;

    const int m0 = blockIdx.y * BM;
    const int n0 = blockIdx.x * BN;

    const float* Ab = A + (size_t)m0 * K;
    const float* Wb = W + n0;

    // per-lane ldmatrix row offset within the A tile (bytes):
    // row = (lane&15), col-quad = (lane>>4) -> +16B
    const uint32_t lmOff = ((uint32_t)(wm * 64 + (lane & 15)) * APAD) * 4u
                         + ((uint32_t)(lane >> 4)) * 16u;

    float acc[4][4][4];
#pragma unroll
    for (int i = 0; i < 4; i++)
#pragma unroll
        for (int j = 0; j < 4; j++)
#pragma unroll
            for (int r = 0; r < 4; r++) acc[i][j][r] = 0.0f;

    const int NT = K / BK;

    // prologue: stages 0..STAGES-2
#pragma unroll
    for (int s = 0; s < STAGES - 1; s++)
        gemm_load_tile(&sm[s], Ab, Wb, K, N, s * BK, tid);

    for (int kt = 0; kt < NT; kt++) {
        const int rem = NT - 1 - kt;
        if (rem >= STAGES - 2)      CP_WAITG(STAGES - 2);
        else if (rem == 1)          CP_WAITG(1);
        else                        CP_WAITG(0);
        __syncthreads();

        if (kt + STAGES - 1 < NT)
            gemm_load_tile(&sm[(kt + STAGES - 1) % STAGES], Ab, Wb, K, N,
                           (kt + STAGES - 1) * BK, tid);

        const SmemTile& S = sm[kt % STAGES];
        const uint32_t aBase = smem_u32(&S) + lmOff;
#pragma unroll
        for (int ks = 0; ks < 2; ks++) {
            const int kk = ks * 8;
            uint32_t af[4][4], bf[4][2];
#pragma unroll
            for (int mf = 0; mf < 4; mf++)
                LDSM_X4(af[mf], aBase + (uint32_t)(mf * 16 * APAD * 4) + (uint32_t)(ks * 32));
#pragma unroll
            for (int nf = 0; nf < 4; nf++) {
                const int cB = wn * 32 + nf * 8 + g;
                bf[nf][0] = __float_as_uint(S.Bs[kk + t][cB]);
                bf[nf][1] = __float_as_uint(S.Bs[kk + t + 4][cB]);
            }
#pragma unroll
            for (int mf = 0; mf < 4; mf++)
#pragma unroll
                for (int nf = 0; nf < 4; nf++)
                    mma_tf32(acc[mf][nf], af[mf], bf[nf]);
        }
    }

#pragma unroll
    for (int mf = 0; mf < 4; mf++) {
        const int row = m0 + wm * 64 + mf * 16 + g;
#pragma unroll
        for (int nf = 0; nf < 4; nf++) {
            const int col = n0 + wn * 32 + nf * 8 + 2 * t;
            const float b0 = bias[col], b1 = bias[col + 1];
            float2 v0 = { acc[mf][nf][0] + b0, acc[mf][nf][1] + b1 };
            float2 v1 = { acc[mf][nf][2] + b0, acc[mf][nf][3] + b1 };
            *(float2*)(C + (size_t)row * N + col) = v0;
            *(float2*)(C + (size_t)(row + 8) * N + col) = v1;
        }
    }
}

// ---------------------------------------------------------------------------
// Tensor-core flash attention: bf16 3-term split, ALiBi + causal (unchanged).
// Epilogue stores tf32-ROUNDED values (feeds the pre-rounded out-proj GEMM).
// ---------------------------------------------------------------------------
#define FST 36
#define FARR (64 * FST)
#define FLASH_SMEM (6 * FARR * 4)

__global__ __launch_bounds__(128)
void flash_mma(const float* __restrict__ qkv, float* __restrict__ out) {
    extern __shared__ uint32_t fsm[];
    uint32_t* QH = fsm;
    uint32_t* QL = QH + FARR;
    uint32_t* KH = QL + FARR;
    uint32_t* KL = KH + FARR;
    uint32_t* VH = KL + FARR;
    uint32_t* VL = VH + FARR;

    const int tid = threadIdx.x;
    const int wid = tid >> 5, lane = tid & 31;
    const int g = lane >> 2, t = lane & 3;

    const int qb = blockIdx.x;
    const int bh = blockIdx.y;
    const int b = bh >> 5;
    const int h = bh & 31;

    const float slope = exp2f(-0.25f * (float)(h + 1));
    const float scale = 8.0f / (float)D_;

    const size_t base = (size_t)b * T_ * THREE_E;
    const float* Qg = qkv + base + (size_t)h * D_;
    const float* Kg = qkv + base + E_ + (size_t)h * D_;
    const float* Vg = qkv + base + 2 * E_ + (size_t)h * D_;

    const int q0 = qb * 64;

    for (int i = tid; i < 64 * 32; i += 128) {
        int r = i >> 5, dp = i & 31;
        const float* p = Qg + (size_t)(q0 + r) * THREE_E + dp * 2;
        uint32_t hi, lo;
        split2(p[0] * scale, p[1] * scale, hi, lo);
        QH[r * FST + dp] = hi;
        QL[r * FST + dp] = lo;
    }

    float o[8][4];
#pragma unroll
    for (int nf = 0; nf < 8; nf++)
#pragma unroll
        for (int r = 0; r < 4; r++) o[nf][r] = 0.0f;
    float m0 = -1e30f, m1 = -1e30f, l0 = 0.0f, l1 = 0.0f;

    const int rW = wid * 16;
    const int qg0 = q0 + rW + g;
    const int qg1 = qg0 + 8;

    for (int kb = 0; kb <= qb; kb++) {
        __syncthreads();
        for (int i = tid; i < 64 * 32; i += 128) {
            int r = i >> 5, dp = i & 31;
            const float* p = Kg + (size_t)(kb * 64 + r) * THREE_E + dp * 2;
            uint32_t hi, lo;
            split2(p[0], p[1], hi, lo);
            KH[r * FST + dp] = hi;
            KL[r * FST + dp] = lo;
        }
        for (int i = tid; i < 64 * 32; i += 128) {
            int d = i & 63, kp = i >> 6;
            const float* p = Vg + (size_t)(kb * 64 + kp * 2) * THREE_E + d;
            uint32_t hi, lo;
            split2(p[0], p[THREE_E], hi, lo);
            VH[d * FST + kp] = hi;
            VL[d * FST + kp] = lo;
        }
        __syncthreads();

        float c[8][4];
#pragma unroll
        for (int nf = 0; nf < 8; nf++)
#pragma unroll
            for (int r = 0; r < 4; r++) c[nf][r] = 0.0f;

#pragma unroll
        for (int kt = 0; kt < 4; kt++) {
            uint32_t ah[4], al[4];
            ah[0] = QH[(rW + g) * FST + kt * 8 + t];
            ah[1] = QH[(rW + g + 8) * FST + kt * 8 + t];
            ah[2] = QH[(rW + g) * FST + kt * 8 + t + 4];
            ah[3] = QH[(rW + g + 8) * FST + kt * 8 + t + 4];
            al[0] = QL[(rW + g) * FST + kt * 8 + t];
            al[1] = QL[(rW + g + 8) * FST + kt * 8 + t];
            al[2] = QL[(rW + g) * FST + kt * 8 + t + 4];
            al[3] = QL[(rW + g + 8) * FST + kt * 8 + t + 4];
#pragma unroll
            for (int nf = 0; nf < 8; nf++) {
                const int rB = (8 * nf + g) * FST + kt * 8 + t;
                uint32_t bh0 = KH[rB], bh1 = KH[rB + 4];
                uint32_t bl0 = KL[rB], bl1 = KL[rB + 4];
                mma_bf16(c[nf], ah, bh0, bh1);
                mma_bf16(c[nf], al, bh0, bh1);
                mma_bf16(c[nf], ah, bl0, bl1);
            }
        }

#pragma unroll
        for (int nf = 0; nf < 8; nf++) {
            const int col0 = kb * 64 + 8 * nf + 2 * t;
            const int col1 = col0 + 1;
            c[nf][0] = (col0 > qg0) ? -1e30f : c[nf][0] + slope * (float)(col0 - qg0);
            c[nf][1] = (col1 > qg0) ? -1e30f : c[nf][1] + slope * (float)(col1 - qg0);
            c[nf][2] = (col0 > qg1) ? -1e30f : c[nf][2] + slope * (float)(col0 - qg1);
            c[nf][3] = (col1 > qg1) ? -1e30f : c[nf][3] + slope * (float)(col1 - qg1);
        }

        float mx0 = -1e30f, mx1 = -1e30f;
#pragma unroll
        for (int nf = 0; nf < 8; nf++) {
            mx0 = fmaxf(mx0, fmaxf(c[nf][0], c[nf][1]));
            mx1 = fmaxf(mx1, fmaxf(c[nf][2], c[nf][3]));
        }
        mx0 = fmaxf(mx0, __shfl_xor_sync(0xffffffffu, mx0, 1));
        mx0 = fmaxf(mx0, __shfl_xor_sync(0xffffffffu, mx0, 2));
        mx1 = fmaxf(mx1, __shfl_xor_sync(0xffffffffu, mx1, 1));
        mx1 = fmaxf(mx1, __shfl_xor_sync(0xffffffffu, mx1, 2));

        const float mn0 = fmaxf(m0, mx0), mn1 = fmaxf(m1, mx1);
        const float alpha0 = __expf(m0 - mn0), alpha1 = __expf(m1 - mn1);
        m0 = mn0; m1 = mn1;

        float s0 = 0.0f, s1 = 0.0f;
#pragma unroll
        for (int nf = 0; nf < 8; nf++) {
            c[nf][0] = __expf(c[nf][0] - m0);
            c[nf][1] = __expf(c[nf][1] - m0);
            c[nf][2] = __expf(c[nf][2] - m1);
            c[nf][3] = __expf(c[nf][3] - m1);
            s0 += c[nf][0] + c[nf][1];
            s1 += c[nf][2] + c[nf][3];
        }
        s0 += __shfl_xor_sync(0xffffffffu, s0, 1);
        s0 += __shfl_xor_sync(0xffffffffu, s0, 2);
        s1 += __shfl_xor_sync(0xffffffffu, s1, 1);
        s1 += __shfl_xor_sync(0xffffffffu, s1, 2);
        l0 = l0 * alpha0 + s0;
        l1 = l1 * alpha1 + s1;

        uint32_t pah[4][4], pal[4][4];
#pragma unroll
        for (int kt = 0; kt < 4; kt++) {
            split2(c[2 * kt][0],     c[2 * kt][1],     pah[kt][0], pal[kt][0]);
            split2(c[2 * kt][2],     c[2 * kt][3],     pah[kt][1], pal[kt][1]);
            split2(c[2 * kt + 1][0], c[2 * kt + 1][1], pah[kt][2], pal[kt][2]);
            split2(c[2 * kt + 1][2], c[2 * kt + 1][3], pah[kt][3], pal[kt][3]);
        }

#pragma unroll
        for (int nf = 0; nf < 8; nf++) {
            o[nf][0] *= alpha0; o[nf][1] *= alpha0;
            o[nf][2] *= alpha1; o[nf][3] *= alpha1;
        }

#pragma unroll
        for (int kt = 0; kt < 4; kt++) {
#pragma unroll
            for (int nf = 0; nf < 8; nf++) {
                const int rB = (8 * nf + g) * FST + kt * 8 + t;
                uint32_t bh0 = VH[rB], bh1 = VH[rB + 4];
                uint32_t bl0 = VL[rB], bl1 = VL[rB + 4];
                mma_bf16(o[nf], pah[kt], bh0, bh1);
                mma_bf16(o[nf], pal[kt], bh0, bh1);
                mma_bf16(o[nf], pah[kt], bl0, bl1);
            }
        }
    }

    // epilogue: normalize, round to tf32 bits (out-proj GEMM needs no cvt)
    const float inv0 = 1.0f / l0, inv1 = 1.0f / l1;
    float* o0 = out + ((size_t)b * T_ + qg0) * E_ + h * D_;
    float* o1 = out + ((size_t)b * T_ + qg1) * E_ + h * D_;
#pragma unroll
    for (int nf = 0; nf < 8; nf++) {
        const int col = 8 * nf + 2 * t;
        float2 v0 = { __uint_as_float(f2tf32(o[nf][0] * inv0)),
                      __uint_as_float(f2tf32(o[nf][1] * inv0)) };
        float2 v1 = { __uint_as_float(f2tf32(o[nf][2] * inv1)),
                      __uint_as_float(f2tf32(o[nf][3] * inv1)) };
        *(float2*)(o0 + col) = v0;
        *(float2*)(o1 + col) = v1;
    }
}

// ---------------------------------------------------------------------------
extern "C" void kernel_launch(void* const* d_in, const int* in_sizes, int n_in,
                              void* d_out, int out_size) {
    const float* x    = (const float*)d_in[0];
    const float* Wqkv = (const float*)d_in[1];
    const float* bqkv = (const float*)d_in[2];
    const float* Wout = (const float*)d_in[3];
    const float* bout = (const float*)d_in[4];
    float* out = (float*)d_out;

    float *qkv, *att, *rx, *rwq, *rwo;
    cudaGetSymbolAddress((void**)&qkv, g_qkv);
    cudaGetSymbolAddress((void**)&att, g_att);
    cudaGetSymbolAddress((void**)&rx,  g_rx);
    cudaGetSymbolAddress((void**)&rwq, g_rwq);
    cudaGetSymbolAddress((void**)&rwo, g_rwo);

    cudaFuncSetAttribute(flash_mma, cudaFuncAttributeMaxDynamicSharedMemorySize, FLASH_SMEM);
    cudaFuncSetAttribute(mma_gemm, cudaFuncAttributeMaxDynamicSharedMemorySize, GEMM_SMEM);

    // 0) pre-round inputs/weights to tf32 bit patterns
    {
        int n4;
        n4 = (B_ * T_ * E_) / 4;
        round_tf32<<<(n4 + 255) / 256, 256>>>((const float4*)x, (float4*)rx, n4);
        n4 = (E_ * THREE_E) / 4;
        round_tf32<<<(n4 + 255) / 256, 256>>>((const float4*)Wqkv, (float4*)rwq, n4);
        n4 = (E_ * E_) / 4;
        round_tf32<<<(n4 + 255) / 256, 256>>>((const float4*)Wout, (float4*)rwo, n4);
    }

    // 1) QKV projection (tf32 tensor cores, pre-rounded operands)
    mma_gemm<<<dim3(THREE_E / BN, (B_ * T_) / BM), NTHR, GEMM_SMEM>>>(
        B_ * T_, THREE_E, E_, rx, rwq, bqkv, qkv);

    // 2) Flash attention (bf16 3-term tensor cores; epilogue rounds att)
    flash_mma<<<dim3(T_ / 64, B_ * H_), 128, FLASH_SMEM>>>(qkv, att);

    // 3) Output projection (tf32 tensor cores, pre-rounded operands)
    mma_gemm<<<dim3(E_ / BN, (B_ * T_) / BM), NTHR, GEMM_SMEM>>>(
        B_ * T_, E_, E_, att, rwo, bout, out);
}

// round 9
// speedup vs baseline: 3.6664x; 1.1407x over previous
#include <cuda_runtime.h>
#include <cuda_bf16.h>
#include <cstdint>

#define B_ 2
#define T_ 2048
#define E_ 2048
#define H_ 32
#define D_ 64
#define THREE_E (3 * E_)

// Scratch (no allocs allowed anywhere).
__device__ float g_qkv[(size_t)B_ * T_ * THREE_E];   // 96 MB
__device__ float g_att[(size_t)B_ * T_ * E_];        // 32 MB (tf32-rounded by flash epilogue)
__device__ float g_rx[(size_t)B_ * T_ * E_];         // 32 MB
__device__ float g_rwq[(size_t)E_ * THREE_E];        // 48 MB
__device__ float g_rwo[(size_t)E_ * E_];             // 16 MB
// pre-split bf16x2 arrays (16 MB each)
#define SPLN ((size_t)B_ * H_ * T_ * 32)
__device__ uint32_t g_QH[SPLN], g_QL[SPLN];
__device__ uint32_t g_KH[SPLN], g_KL[SPLN];
__device__ uint32_t g_VH[SPLN], g_VL[SPLN];          // layout [bh][d][T/2]

// ---------------------------------------------------------------------------
// helpers
// ---------------------------------------------------------------------------
__device__ __forceinline__ uint32_t smem_u32(const void* p) {
    uint32_t a;
    asm("{ .reg .u64 t; cvta.to.shared.u64 t, %1; cvt.u32.u64 %0, t; }" : "=r"(a) : "l"(p));
    return a;
}
#define CP_ASYNC16(dst, src) \
    asm volatile("cp.async.cg.shared.global [%0], [%1], 16;" :: "r"(dst), "l"(src))
#define CP_COMMIT() asm volatile("cp.async.commit_group;" ::: "memory")
#define CP_WAITG(n) asm volatile("cp.async.wait_group %0;" :: "n"(n) : "memory")

#define LDSM_X4(r, a)                                                            \
    asm volatile("ldmatrix.sync.aligned.m8n8.x4.shared.b16 {%0,%1,%2,%3}, [%4];" \
        : "=r"((r)[0]), "=r"((r)[1]), "=r"((r)[2]), "=r"((r)[3]) : "r"(a))

__device__ __forceinline__ uint32_t f2tf32(float x) {
    uint32_t r;
    asm("cvt.rna.tf32.f32 %0, %1;" : "=r"(r) : "f"(x));
    return r;
}

__device__ __forceinline__ void mma_tf32(float* c, const uint32_t* a, const uint32_t* b) {
    asm volatile(
        "mma.sync.aligned.m16n8k8.row.col.f32.tf32.tf32.f32 "
        "{%0,%1,%2,%3}, {%4,%5,%6,%7}, {%8,%9}, {%0,%1,%2,%3};"
        : "+f"(c[0]), "+f"(c[1]), "+f"(c[2]), "+f"(c[3])
        : "r"(a[0]), "r"(a[1]), "r"(a[2]), "r"(a[3]), "r"(b[0]), "r"(b[1]));
}

__device__ __forceinline__ void mma_bf16(float* c, const uint32_t* a, uint32_t b0, uint32_t b1) {
    asm volatile(
        "mma.sync.aligned.m16n8k16.row.col.f32.bf16.bf16.f32 "
        "{%0,%1,%2,%3}, {%4,%5,%6,%7}, {%8,%9}, {%0,%1,%2,%3};"
        : "+f"(c[0]), "+f"(c[1]), "+f"(c[2]), "+f"(c[3])
        : "r"(a[0]), "r"(a[1]), "r"(a[2]), "r"(a[3]), "r"(b0), "r"(b1));
}

__device__ __forceinline__ void split2(float x, float y, uint32_t& hi, uint32_t& lo) {
    __nv_bfloat16 hx = __float2bfloat16(x);
    __nv_bfloat16 hy = __float2bfloat16(y);
    __nv_bfloat16 lx = __float2bfloat16(x - __bfloat162float(hx));
    __nv_bfloat16 ly = __float2bfloat16(y - __bfloat162float(hy));
    hi = ((uint32_t)__bfloat16_as_ushort(hy) << 16) | __bfloat16_as_ushort(hx);
    lo = ((uint32_t)__bfloat16_as_ushort(ly) << 16) | __bfloat16_as_ushort(lx);
}

// ---------------------------------------------------------------------------
// Pre-round fp32 -> tf32 bit patterns
// ---------------------------------------------------------------------------
__global__ void round_tf32(const float4* __restrict__ in, float4* __restrict__ out, int n4) {
    int i = blockIdx.x * blockDim.x + threadIdx.x;
    if (i < n4) {
        float4 v = in[i];
        float4 r;
        r.x = __uint_as_float(f2tf32(v.x));
        r.y = __uint_as_float(f2tf32(v.y));
        r.z = __uint_as_float(f2tf32(v.z));
        r.w = __uint_as_float(f2tf32(v.w));
        out[i] = r;
    }
}

// ---------------------------------------------------------------------------
// prep_split: qkv -> split bf16x2 arrays.
// Q/K: [bh][t][dp] (dp = d-pair).  V: transposed [bh][d][kp] (kp = t-pair).
// grid (T/64, B*H), 128 threads.
// ---------------------------------------------------------------------------
__global__ __launch_bounds__(128)
void prep_split(const float* __restrict__ qkv,
                uint32_t* __restrict__ QH, uint32_t* __restrict__ QL,
                uint32_t* __restrict__ KH, uint32_t* __restrict__ KL,
                uint32_t* __restrict__ VH, uint32_t* __restrict__ VL) {
    const int tid = threadIdx.x;
    const int tb = blockIdx.x, bh = blockIdx.y;
    const int b = bh >> 5, h = bh & 31;
    const float scale = 8.0f / (float)D_;
    const size_t base = (size_t)b * T_ * THREE_E + (size_t)h * D_;

    const int dp = tid & 31;
    for (int r = tid >> 5; r < 64; r += 4) {
        const int t = tb * 64 + r;
        const float* pq = qkv + base + (size_t)t * THREE_E + dp * 2;
        uint32_t hi, lo;
        split2(pq[0] * scale, pq[1] * scale, hi, lo);
        const size_t oi = ((size_t)bh * T_ + t) * 32 + dp;
        QH[oi] = hi; QL[oi] = lo;
        const float* pk = pq + E_;
        split2(pk[0], pk[1], hi, lo);
        KH[oi] = hi; KL[oi] = lo;
    }
    const int kp = tid & 31;
    for (int d = tid >> 5; d < 64; d += 4) {
        const float* pv = qkv + base + 2 * E_ + (size_t)(tb * 64 + 2 * kp) * THREE_E + d;
        uint32_t hi, lo;
        split2(pv[0], pv[THREE_E], hi, lo);
        const size_t oi = ((size_t)bh * 64 + d) * (T_ / 2) + tb * 32 + kp;
        VH[oi] = hi; VL[oi] = lo;
    }
}

// ---------------------------------------------------------------------------
// tf32 tensor-core GEMM (round-8 proven, unchanged)
// ---------------------------------------------------------------------------
#define BM 128
#define BN 128
#define BK 16
#define APAD 20
#define BPAD 136
#define NTHR 256
#define STAGES 4

struct SmemTile {
    float As[BM][APAD];
    float Bs[BK][BPAD];
};
#define GEMM_SMEM (STAGES * (int)sizeof(SmemTile))

__device__ __forceinline__ void gemm_load_tile(SmemTile* st,
                                               const float* __restrict__ Ab,
                                               const float* __restrict__ Wb,
                                               int K, int N, int k0, int tid) {
#pragma unroll
    for (int it = 0; it < 2; it++) {
        int idx = tid + NTHR * it;
        int m = idx >> 2, kc = idx & 3;
        CP_ASYNC16(smem_u32(&st->As[m][kc * 4]), Ab + (size_t)m * K + k0 + kc * 4);
    }
#pragma unroll
    for (int it = 0; it < 2; it++) {
        int idx = tid + NTHR * it;
        int k = idx >> 5, c = idx & 31;
        CP_ASYNC16(smem_u32(&st->Bs[k][c * 4]), Wb + (size_t)(k0 + k) * N + c * 4);
    }
    CP_COMMIT();
}

__global__ __launch_bounds__(NTHR, 2)
void mma_gemm(int M, int N, int K,
              const float* __restrict__ A,
              const float* __restrict__ W,
              const float* __restrict__ bias,
              float* __restrict__ C) {
    extern __shared__ SmemTile sm[];

    const int tid = threadIdx.x;
    const int wid = tid >> 5, lane = tid & 31;
    const int wm = wid >> 2, wn = wid & 3;
    const int g = lane >> 2, t = lane & 3;

    const int m0 = blockIdx.y * BM;
    const int n0 = blockIdx.x * BN;

    const float* Ab = A + (size_t)m0 * K;
    const float* Wb = W + n0;

    const uint32_t lmOff = ((uint32_t)(wm * 64 + (lane & 15)) * APAD) * 4u
                         + ((uint32_t)(lane >> 4)) * 16u;

    float acc[4][4][4];
#pragma unroll
    for (int i = 0; i < 4; i++)
#pragma unroll
        for (int j = 0; j < 4; j++)
#pragma unroll
            for (int r = 0; r < 4; r++) acc[i][j][r] = 0.0f;

    const int NT = K / BK;

#pragma unroll
    for (int s = 0; s < STAGES - 1; s++)
        gemm_load_tile(&sm[s], Ab, Wb, K, N, s * BK, tid);

    for (int kt = 0; kt < NT; kt++) {
        const int rem = NT - 1 - kt;
        if (rem >= STAGES - 2)      CP_WAITG(STAGES - 2);
        else if (rem == 1)          CP_WAITG(1);
        else                        CP_WAITG(0);
        __syncthreads();

        if (kt + STAGES - 1 < NT)
            gemm_load_tile(&sm[(kt + STAGES - 1) % STAGES], Ab, Wb, K, N,
                           (kt + STAGES - 1) * BK, tid);

        const SmemTile& S = sm[kt % STAGES];
        const uint32_t aBase = smem_u32(&S) + lmOff;
#pragma unroll
        for (int ks = 0; ks < 2; ks++) {
            const int kk = ks * 8;
            uint32_t af[4][4], bf[4][2];
#pragma unroll
            for (int mf = 0; mf < 4; mf++)
                LDSM_X4(af[mf], aBase + (uint32_t)(mf * 16 * APAD * 4) + (uint32_t)(ks * 32));
#pragma unroll
            for (int nf = 0; nf < 4; nf++) {
                const int cB = wn * 32 + nf * 8 + g;
                bf[nf][0] = __float_as_uint(S.Bs[kk + t][cB]);
                bf[nf][1] = __float_as_uint(S.Bs[kk + t + 4][cB]);
            }
#pragma unroll
            for (int mf = 0; mf < 4; mf++)
#pragma unroll
                for (int nf = 0; nf < 4; nf++)
                    mma_tf32(acc[mf][nf], af[mf], bf[nf]);
        }
    }

#pragma unroll
    for (int mf = 0; mf < 4; mf++) {
        const int row = m0 + wm * 64 + mf * 16 + g;
#pragma unroll
        for (int nf = 0; nf < 4; nf++) {
            const int col = n0 + wn * 32 + nf * 8 + 2 * t;
            const float b0 = bias[col], b1 = bias[col + 1];
            float2 v0 = { acc[mf][nf][0] + b0, acc[mf][nf][1] + b1 };
            float2 v1 = { acc[mf][nf][2] + b0, acc[mf][nf][3] + b1 };
            *(float2*)(C + (size_t)row * N + col) = v0;
            *(float2*)(C + (size_t)(row + 8) * N + col) = v1;
        }
    }
}

// ---------------------------------------------------------------------------
// Flash attention: pre-split inputs, Q in registers, cp.async double-buffered
// K/V tiles. bf16 3-term, ALiBi + causal. Epilogue rounds to tf32.
// Smem per stage: KH,KL,VH,VL each [64][36] u32.
// ---------------------------------------------------------------------------
#define FST 36
#define FARR (64 * FST)
#define FARRB (FARR * 4)
#define FLASH_SMEM (2 * 4 * FARRB)

__device__ __forceinline__ void load_kv_tile(uint32_t sbase,
                                             const uint32_t* __restrict__ kh,
                                             const uint32_t* __restrict__ kl,
                                             const uint32_t* __restrict__ vh,
                                             const uint32_t* __restrict__ vl,
                                             int tid) {
#pragma unroll
    for (int i = 0; i < 4; i++) {
        int idx = tid + 128 * i, r = idx >> 3, c = (idx & 7) * 4;
        CP_ASYNC16(sbase + (uint32_t)(r * FST + c) * 4u, kh + (size_t)r * 32 + c);
    }
#pragma unroll
    for (int i = 0; i < 4; i++) {
        int idx = tid + 128 * i, r = idx >> 3, c = (idx & 7) * 4;
        CP_ASYNC16(sbase + FARRB + (uint32_t)(r * FST + c) * 4u, kl + (size_t)r * 32 + c);
    }
#pragma unroll
    for (int i = 0; i < 4; i++) {
        int idx = tid + 128 * i, r = idx >> 3, c = (idx & 7) * 4;
        CP_ASYNC16(sbase + 2 * FARRB + (uint32_t)(r * FST + c) * 4u, vh + (size_t)r * (T_ / 2) + c);
    }
#pragma unroll
    for (int i = 0; i < 4; i++) {
        int idx = tid + 128 * i, r = idx >> 3, c = (idx & 7) * 4;
        CP_ASYNC16(sbase + 3 * FARRB + (uint32_t)(r * FST + c) * 4u, vl + (size_t)r * (T_ / 2) + c);
    }
    CP_COMMIT();
}

__global__ __launch_bounds__(128)
void flash_mma(const uint32_t* __restrict__ gQH, const uint32_t* __restrict__ gQL,
               const uint32_t* __restrict__ gKH, const uint32_t* __restrict__ gKL,
               const uint32_t* __restrict__ gVH, const uint32_t* __restrict__ gVL,
               float* __restrict__ out) {
    extern __shared__ uint32_t fsm[];
    const uint32_t sbase = smem_u32(fsm);

    const int tid = threadIdx.x;
    const int wid = tid >> 5, lane = tid & 31;
    const int g = lane >> 2, t = lane & 3;

    const int qb = blockIdx.x;
    const int bh = blockIdx.y;
    const int b = bh >> 5;
    const int h = bh & 31;

    const float slope = exp2f(-0.25f * (float)(h + 1));
    const int q0 = qb * 64;
    const int rW = wid * 16;
    const int qg0 = q0 + rW + g;
    const int qg1 = qg0 + 8;

    // K/V tile base pointers for this (b,h)
    const uint32_t* bKH = gKH + (size_t)bh * T_ * 32;
    const uint32_t* bKL = gKL + (size_t)bh * T_ * 32;
    const uint32_t* bVH = gVH + (size_t)bh * 64 * (T_ / 2);
    const uint32_t* bVL = gVL + (size_t)bh * 64 * (T_ / 2);

    // Q fragments -> registers (once)
    uint32_t qah[4][4], qal[4][4];
    {
        const uint32_t* q0p = gQH + ((size_t)bh * T_ + qg0) * 32;
        const uint32_t* q1p = gQH + ((size_t)bh * T_ + qg1) * 32;
        const uint32_t* q0l = gQL + ((size_t)bh * T_ + qg0) * 32;
        const uint32_t* q1l = gQL + ((size_t)bh * T_ + qg1) * 32;
#pragma unroll
        for (int kt = 0; kt < 4; kt++) {
            qah[kt][0] = q0p[kt * 8 + t];
            qah[kt][1] = q1p[kt * 8 + t];
            qah[kt][2] = q0p[kt * 8 + t + 4];
            qah[kt][3] = q1p[kt * 8 + t + 4];
            qal[kt][0] = q0l[kt * 8 + t];
            qal[kt][1] = q1l[kt * 8 + t];
            qal[kt][2] = q0l[kt * 8 + t + 4];
            qal[kt][3] = q1l[kt * 8 + t + 4];
        }
    }

    float o[8][4];
#pragma unroll
    for (int nf = 0; nf < 8; nf++)
#pragma unroll
        for (int r = 0; r < 4; r++) o[nf][r] = 0.0f;
    float m0 = -1e30f, m1 = -1e30f, l0 = 0.0f, l1 = 0.0f;

    // prologue: load tile 0 into stage 0
    load_kv_tile(sbase, bKH, bKL, bVH, bVL, tid);

    for (int kb = 0; kb <= qb; kb++) {
        CP_WAITG(0);
        __syncthreads();
        if (kb < qb)
            load_kv_tile(sbase + ((kb + 1) & 1) * 4 * FARRB,
                         bKH + (size_t)(kb + 1) * 64 * 32,
                         bKL + (size_t)(kb + 1) * 64 * 32,
                         bVH + (size_t)(kb + 1) * 32,
                         bVL + (size_t)(kb + 1) * 32, tid);

        const uint32_t* sKH = fsm + (kb & 1) * 4 * FARR;
        const uint32_t* sKL = sKH + FARR;
        const uint32_t* sVH = sKH + 2 * FARR;
        const uint32_t* sVL = sKH + 3 * FARR;

        // ---- S = Q @ K^T (3-term bf16) ----
        float c[8][4];
#pragma unroll
        for (int nf = 0; nf < 8; nf++)
#pragma unroll
            for (int r = 0; r < 4; r++) c[nf][r] = 0.0f;

#pragma unroll
        for (int kt = 0; kt < 4; kt++) {
#pragma unroll
            for (int nf = 0; nf < 8; nf++) {
                const int rB = (8 * nf + g) * FST + kt * 8 + t;
                uint32_t bh0 = sKH[rB], bh1 = sKH[rB + 4];
                uint32_t bl0 = sKL[rB], bl1 = sKL[rB + 4];
                mma_bf16(c[nf], qah[kt], bh0, bh1);
                mma_bf16(c[nf], qal[kt], bh0, bh1);
                mma_bf16(c[nf], qah[kt], bl0, bl1);
            }
        }

        // ---- mask + ALiBi ----
#pragma unroll
        for (int nf = 0; nf < 8; nf++) {
            const int col0 = kb * 64 + 8 * nf + 2 * t;
            const int col1 = col0 + 1;
            c[nf][0] = (col0 > qg0) ? -1e30f : c[nf][0] + slope * (float)(col0 - qg0);
            c[nf][1] = (col1 > qg0) ? -1e30f : c[nf][1] + slope * (float)(col1 - qg0);
            c[nf][2] = (col0 > qg1) ? -1e30f : c[nf][2] + slope * (float)(col0 - qg1);
            c[nf][3] = (col1 > qg1) ? -1e30f : c[nf][3] + slope * (float)(col1 - qg1);
        }

        // ---- online softmax ----
        float mx0 = -1e30f, mx1 = -1e30f;
#pragma unroll
        for (int nf = 0; nf < 8; nf++) {
            mx0 = fmaxf(mx0, fmaxf(c[nf][0], c[nf][1]));
            mx1 = fmaxf(mx1, fmaxf(c[nf][2], c[nf][3]));
        }
        mx0 = fmaxf(mx0, __shfl_xor_sync(0xffffffffu, mx0, 1));
        mx0 = fmaxf(mx0, __shfl_xor_sync(0xffffffffu, mx0, 2));
        mx1 = fmaxf(mx1, __shfl_xor_sync(0xffffffffu, mx1, 1));
        mx1 = fmaxf(mx1, __shfl_xor_sync(0xffffffffu, mx1, 2));

        const float mn0 = fmaxf(m0, mx0), mn1 = fmaxf(m1, mx1);
        const float alpha0 = __expf(m0 - mn0), alpha1 = __expf(m1 - mn1);
        m0 = mn0; m1 = mn1;

        float s0 = 0.0f, s1 = 0.0f;
#pragma unroll
        for (int nf = 0; nf < 8; nf++) {
            c[nf][0] = __expf(c[nf][0] - m0);
            c[nf][1] = __expf(c[nf][1] - m0);
            c[nf][2] = __expf(c[nf][2] - m1);
            c[nf][3] = __expf(c[nf][3] - m1);
            s0 += c[nf][0] + c[nf][1];
            s1 += c[nf][2] + c[nf][3];
        }
        s0 += __shfl_xor_sync(0xffffffffu, s0, 1);
        s0 += __shfl_xor_sync(0xffffffffu, s0, 2);
        s1 += __shfl_xor_sync(0xffffffffu, s1, 1);
        s1 += __shfl_xor_sync(0xffffffffu, s1, 2);
        l0 = l0 * alpha0 + s0;
        l1 = l1 * alpha1 + s1;

        // pack P into A-fragments
        uint32_t pah[4][4], pal[4][4];
#pragma unroll
        for (int kt = 0; kt < 4; kt++) {
            split2(c[2 * kt][0],     c[2 * kt][1],     pah[kt][0], pal[kt][0]);
            split2(c[2 * kt][2],     c[2 * kt][3],     pah[kt][1], pal[kt][1]);
            split2(c[2 * kt + 1][0], c[2 * kt + 1][1], pah[kt][2], pal[kt][2]);
            split2(c[2 * kt + 1][2], c[2 * kt + 1][3], pah[kt][3], pal[kt][3]);
        }

#pragma unroll
        for (int nf = 0; nf < 8; nf++) {
            o[nf][0] *= alpha0; o[nf][1] *= alpha0;
            o[nf][2] *= alpha1; o[nf][3] *= alpha1;
        }

        // ---- O += P @ V (3-term bf16) ----
#pragma unroll
        for (int kt = 0; kt < 4; kt++) {
#pragma unroll
            for (int nf = 0; nf < 8; nf++) {
                const int rB = (8 * nf + g) * FST + kt * 8 + t;
                uint32_t bh0 = sVH[rB], bh1 = sVH[rB + 4];
                uint32_t bl0 = sVL[rB], bl1 = sVL[rB + 4];
                mma_bf16(o[nf], pah[kt], bh0, bh1);
                mma_bf16(o[nf], pal[kt], bh0, bh1);
                mma_bf16(o[nf], pah[kt], bl0, bl1);
            }
        }
    }

    // epilogue: normalize, round to tf32 bits
    const float inv0 = 1.0f / l0, inv1 = 1.0f / l1;
    float* o0 = out + ((size_t)b * T_ + qg0) * E_ + h * D_;
    float* o1 = out + ((size_t)b * T_ + qg1) * E_ + h * D_;
#pragma unroll
    for (int nf = 0; nf < 8; nf++) {
        const int col = 8 * nf + 2 * t;
        float2 v0 = { __uint_as_float(f2tf32(o[nf][0] * inv0)),
                      __uint_as_float(f2tf32(o[nf][1] * inv0)) };
        float2 v1 = { __uint_as_float(f2tf32(o[nf][2] * inv1)),
                      __uint_as_float(f2tf32(o[nf][3] * inv1)) };
        *(float2*)(o0 + col) = v0;
        *(float2*)(o1 + col) = v1;
    }
}

// ---------------------------------------------------------------------------
extern "C" void kernel_launch(void* const* d_in, const int* in_sizes, int n_in,
                              void* d_out, int out_size) {
    const float* x    = (const float*)d_in[0];
    const float* Wqkv = (const float*)d_in[1];
    const float* bqkv = (const float*)d_in[2];
    const float* Wout = (const float*)d_in[3];
    const float* bout = (const float*)d_in[4];
    float* out = (float*)d_out;

    float *qkv, *att, *rx, *rwq, *rwo;
    uint32_t *pQH, *pQL, *pKH, *pKL, *pVH, *pVL;
    cudaGetSymbolAddress((void**)&qkv, g_qkv);
    cudaGetSymbolAddress((void**)&att, g_att);
    cudaGetSymbolAddress((void**)&rx,  g_rx);
    cudaGetSymbolAddress((void**)&rwq, g_rwq);
    cudaGetSymbolAddress((void**)&rwo, g_rwo);
    cudaGetSymbolAddress((void**)&pQH, g_QH);
    cudaGetSymbolAddress((void**)&pQL, g_QL);
    cudaGetSymbolAddress((void**)&pKH, g_KH);
    cudaGetSymbolAddress((void**)&pKL, g_KL);
    cudaGetSymbolAddress((void**)&pVH, g_VH);
    cudaGetSymbolAddress((void**)&pVL, g_VL);

    cudaFuncSetAttribute(flash_mma, cudaFuncAttributeMaxDynamicSharedMemorySize, FLASH_SMEM);
    cudaFuncSetAttribute(mma_gemm, cudaFuncAttributeMaxDynamicSharedMemorySize, GEMM_SMEM);

    // 0) pre-round inputs/weights to tf32 bit patterns
    {
        int n4;
        n4 = (B_ * T_ * E_) / 4;
        round_tf32<<<(n4 + 255) / 256, 256>>>((const float4*)x, (float4*)rx, n4);
        n4 = (E_ * THREE_E) / 4;
        round_tf32<<<(n4 + 255) / 256, 256>>>((const float4*)Wqkv, (float4*)rwq, n4);
        n4 = (E_ * E_) / 4;
        round_tf32<<<(n4 + 255) / 256, 256>>>((const float4*)Wout, (float4*)rwo, n4);
    }

    // 1) QKV projection
    mma_gemm<<<dim3(THREE_E / BN, (B_ * T_) / BM), NTHR, GEMM_SMEM>>>(
        B_ * T_, THREE_E, E_, rx, rwq, bqkv, qkv);

    // 1b) split Q/K/V to bf16 hi/lo fragment arrays
    prep_split<<<dim3(T_ / 64, B_ * H_), 128>>>(qkv, pQH, pQL, pKH, pKL, pVH, pVL);

    // 2) Flash attention (pre-split, cp.async double-buffered)
    flash_mma<<<dim3(T_ / 64, B_ * H_), 128, FLASH_SMEM>>>(
        pQH, pQL, pKH, pKL, pVH, pVL, att);

    // 3) Output projection
    mma_gemm<<<dim3(E_ / BN, (B_ * T_) / BM), NTHR, GEMM_SMEM>>>(
        B_ * T_, E_, E_, att, rwo, bout, out);
}